// round 4
// baseline (speedup 1.0000x reference)
#include <cuda_runtime.h>
#include <cstdint>

#define DIMC  1024
#define NH    16
#define HD    64
#define BATCH 4
#define SEQ   2048
#define MTOT  (BATCH*SEQ)   // 8192

// ---------------- scratch (device globals; no allocation allowed) ----------
__device__ float g_q[(size_t)BATCH*NH*SEQ*HD];     // [b*NH+h][t][d]  (tf32-rounded)
__device__ float g_k[(size_t)BATCH*NH*SEQ*HD];
__device__ float g_v[(size_t)BATCH*NH*SEQ*HD];
__device__ float g_attn[(size_t)MTOT*DIMC];        // [b*T+t][h*64+d]

// ---------------- helpers ---------------------------------------------------
__device__ __forceinline__ uint32_t f2tf(float f){
    uint32_t u; asm("cvt.rna.tf32.f32 %0, %1;" : "=r"(u) : "f"(f)); return u;
}

__device__ __forceinline__ void mma_tf32(float c[4], const uint32_t a[4], const uint32_t b[2]){
    asm volatile(
        "mma.sync.aligned.m16n8k8.row.col.f32.tf32.tf32.f32 "
        "{%0,%1,%2,%3}, {%4,%5,%6,%7}, {%8,%9}, {%0,%1,%2,%3};"
        : "+f"(c[0]), "+f"(c[1]), "+f"(c[2]), "+f"(c[3])
        : "r"(a[0]), "r"(a[1]), "r"(a[2]), "r"(a[3]), "r"(b[0]), "r"(b[1]));
}

// ============================================================================
// GEMM: C[M,N] = A[M,K] @ W[N,K]^T  (both K-major, K=1024), legacy tf32 mma.
// Permuted-fragment smem layout:
//   A value (16g+rr, 8ks+cc) -> word (g*4+ks)*136 + ((rr&7)*4 + (cc&3))*4
//                                     + (rr>>3) + 2*(cc>>2)
//   -> one LDS.128 per (mt,ks) yields exactly {a0,a1,a2,a3}.
//   B value (8n+nr, 8ks+cc)  -> word (n*4+ks)*66 + ((nr)*4 + (cc&3))*2 + (cc>>2)
//   -> one LDS.64 per (nt,ks) yields {b0,b1}.
// 2-stage smem double buffer, register-staged LDG, ONE syncthreads per ktile.
// ============================================================================
#define GTM 128
#define GTN 128
#define GTK 32
#define GNT (DIMC/GTK)          // 32
#define GPAD_A 136
#define GPAD_B 66
#define A_WORDS (32*GPAD_A)     // 4352  (17408 B)
#define B_WORDS (64*GPAD_B)     // 4224  (16896 B)
#define STG_WORDS (A_WORDS + B_WORDS)   // 8576
#define GSMEM (2*STG_WORDS*4)           // 68608 B

__device__ __forceinline__ void g_ldg(float4 stA[4], float4 stB[4],
                                      const float* __restrict__ A,
                                      const float* __restrict__ W,
                                      int bm0, int bn0, int k0, int tid){
    #pragma unroll
    for (int p = 0; p < 4; p++){
        int n = tid + p*256;
        int r = n >> 3, c4 = (n & 7) << 2;
        stA[p] = *(const float4*)(A + (size_t)(bm0 + r)*DIMC + k0 + c4);
        stB[p] = *(const float4*)(W + (size_t)(bn0 + r)*DIMC + k0 + c4);
    }
}

__device__ __forceinline__ void g_sts(uint32_t* __restrict__ sA, uint32_t* __restrict__ sB,
                                      const float4 stA[4], const float4 stB[4], int tid){
    #pragma unroll
    for (int p = 0; p < 4; p++){
        int n = tid + p*256;
        int r = n >> 3, ch = n & 7;
        int ks = ch >> 1;
        {   // A: rows 0..127, cols ch*4..ch*4+3
            int g = r >> 4, rr = r & 15;
            uint32_t* d = sA + (g*4 + ks)*GPAD_A + ((rr & 7) << 4)
                             + (rr >> 3) + ((ch & 1) << 1);
            d[0]  = f2tf(stA[p].x);
            d[4]  = f2tf(stA[p].y);
            d[8]  = f2tf(stA[p].z);
            d[12] = f2tf(stA[p].w);
        }
        {   // B
            int ng = r >> 3, nr = r & 7;
            uint32_t* d = sB + (ng*4 + ks)*GPAD_B + (nr << 3) + (ch & 1);
            d[0] = f2tf(stB[p].x);
            d[2] = f2tf(stB[p].y);
            d[4] = f2tf(stB[p].z);
            d[6] = f2tf(stB[p].w);
        }
    }
}

// qkv=1: A=Ain(x), W selected by blockIdx.z among W0/W1/W2, out -> g_q/g_k/g_v
//        (tf32-rounded so attention can skip conversion)
// qkv=0: A=g_attn, W=W0(=wo), out -> Cout plain fp32
__global__ void __launch_bounds__(256)
gemm_tf32p(const float* __restrict__ Ain,
           const float* __restrict__ W0, const float* __restrict__ W1,
           const float* __restrict__ W2,
           float* __restrict__ Cout, int qkv)
{
    extern __shared__ __align__(16) uint32_t sm[];
    int tid = threadIdx.x, lane = tid & 31, warp = tid >> 5;
    int bm0 = blockIdx.y * GTM, bn0 = blockIdx.x * GTN;
    int z = qkv ? blockIdx.z : 0;
    const float* A = qkv ? Ain : g_attn;
    const float* W = (z == 0) ? W0 : (z == 1) ? W1 : W2;

    float c[4][4][4];
    #pragma unroll
    for (int i = 0; i < 4; i++)
        #pragma unroll
        for (int j = 0; j < 4; j++)
            #pragma unroll
            for (int k = 0; k < 4; k++) c[i][j][k] = 0.f;

    float4 stA[4], stB[4];
    g_ldg(stA, stB, A, W, bm0, bn0, 0, tid);
    g_sts(sm, sm + A_WORDS, stA, stB, tid);
    __syncthreads();

    int ga0 = (warp >> 2) * 4;   // A row-group base for this warp
    int gb0 = (warp & 3) * 4;    // B n-group base

    for (int kt = 0; kt < GNT; kt++){
        const uint32_t* sc = sm + (kt & 1)*STG_WORDS;
        if (kt + 1 < GNT) g_ldg(stA, stB, A, W, bm0, bn0, (kt+1)*GTK, tid);

        #pragma unroll
        for (int ks = 0; ks < 4; ks++){
            uint4 av[4]; uint2 bv[4];
            #pragma unroll
            for (int mt = 0; mt < 4; mt++)
                av[mt] = *(const uint4*)(sc + ((ga0 + mt)*4 + ks)*GPAD_A + lane*4);
            #pragma unroll
            for (int nt = 0; nt < 4; nt++)
                bv[nt] = *(const uint2*)(sc + A_WORDS + ((gb0 + nt)*4 + ks)*GPAD_B + lane*2);
            #pragma unroll
            for (int mt = 0; mt < 4; mt++){
                uint32_t af[4] = {av[mt].x, av[mt].y, av[mt].z, av[mt].w};
                #pragma unroll
                for (int nt = 0; nt < 4; nt++){
                    uint32_t bf[2] = {bv[nt].x, bv[nt].y};
                    mma_tf32(c[mt][nt], af, bf);
                }
            }
        }

        if (kt + 1 < GNT){
            uint32_t* sn = sm + ((kt + 1) & 1)*STG_WORDS;
            g_sts(sn, sn + A_WORDS, stA, stB, tid);
        }
        __syncthreads();
    }

    // epilogue
    int wm = (warp >> 2) * 64, wn = (warp & 3) * 32;
    #pragma unroll
    for (int mt = 0; mt < 4; mt++){
        #pragma unroll
        for (int nt = 0; nt < 4; nt++){
            int gr = bm0 + wm + mt*16 + (lane >> 2);
            int gc = bn0 + wn + nt*8 + ((lane & 3) << 1);
            if (qkv){
                float* dst = (z == 0) ? g_q : (z == 1) ? g_k : g_v;
                int bb = gr >> 11, tt = gr & (SEQ - 1);
                int hh = gc >> 6,  dd = gc & (HD - 1);
                size_t off = ((size_t)(bb*NH + hh)*SEQ + tt)*HD + dd;
                float2 v0 = make_float2(__uint_as_float(f2tf(c[mt][nt][0])),
                                        __uint_as_float(f2tf(c[mt][nt][1])));
                float2 v1 = make_float2(__uint_as_float(f2tf(c[mt][nt][2])),
                                        __uint_as_float(f2tf(c[mt][nt][3])));
                *(float2*)(dst + off)         = v0;
                *(float2*)(dst + off + 8*HD)  = v1;
            } else {
                *(float2*)(Cout + (size_t)gr*DIMC + gc)
                    = make_float2(c[mt][nt][0], c[mt][nt][1]);
                *(float2*)(Cout + (size_t)(gr + 8)*DIMC + gc)
                    = make_float2(c[mt][nt][2], c[mt][nt][3]);
            }
        }
    }
}

// ============================================================================
// causal flash attention, tf32 mma, fp32 softmax, permuted-fragment smem
// ============================================================================
#define QT 64
#define KTILE 32
#define APAD 136
#define KPAD 66

__global__ void __launch_bounds__(128)
attn_tf32()
{
    __shared__ __align__(16) uint32_t sQP[32*APAD];  // 17408 B; Q perm, reused as P perm
    __shared__ __align__(16) uint32_t sKp[32*KPAD];  //  8448 B
    __shared__ __align__(16) uint32_t sVp[32*KPAD];  //  8448 B

    int tid  = threadIdx.x;
    int lane = tid & 31;
    int warp = tid >> 5;
    int bh = blockIdx.y;
    int q0 = blockIdx.x * QT;

    const float* Qg = g_q + (size_t)bh*SEQ*HD;
    const float* Kg = g_k + (size_t)bh*SEQ*HD;
    const float* Vg = g_v + (size_t)bh*SEQ*HD;

    // Q tile (64x64, already tf32-rounded) -> permuted smem
    #pragma unroll
    for (int p = 0; p < 8; p++){
        int n = tid + p*128;            // 0..1023 float4-chunks
        int r = n >> 4, ch = n & 15;    // row 0..63, cols ch*4..+3
        float4 v = *(const float4*)(Qg + (size_t)(q0 + r)*HD + (ch << 2));
        int wg = r >> 4, rr = r & 15;
        uint32_t* d = sQP + (wg*8 + (ch >> 1))*APAD + ((rr & 7) << 4)
                         + (rr >> 3) + ((ch & 1) << 1);
        d[0]  = __float_as_uint(v.x);
        d[4]  = __float_as_uint(v.y);
        d[8]  = __float_as_uint(v.z);
        d[12] = __float_as_uint(v.w);
    }
    __syncthreads();

    // preload Q fragments: one LDS.128 per ks
    uint32_t qf[8][4];
    #pragma unroll
    for (int ks = 0; ks < 8; ks++){
        uint4 t = *(const uint4*)(sQP + (warp*8 + ks)*APAD + lane*4);
        qf[ks][0] = t.x; qf[ks][1] = t.y; qf[ks][2] = t.z; qf[ks][3] = t.w;
    }

    float o[8][4];
    #pragma unroll
    for (int i = 0; i < 8; i++)
        #pragma unroll
        for (int j = 0; j < 4; j++) o[i][j] = 0.f;
    float m0 = -1e30f, m1 = -1e30f, l0 = 0.f, l1 = 0.f;

    int nkt = (q0 + QT) / KTILE;
    for (int kt = 0; kt < nkt; kt++){
        __syncthreads();   // prior compute done (incl. Q preload on kt=0)
        int kb = kt*KTILE;
        // fill K,V (32x64 each, pre-rounded) into permuted layouts
        #pragma unroll
        for (int p = 0; p < 4; p++){
            int n = tid + p*128;           // 0..511 chunks
            int r = n >> 4, ch = n & 15;   // key 0..31, d = ch*4..+3
            float4 kv = *(const float4*)(Kg + (size_t)(kb + r)*HD + (ch << 2));
            float4 vv = *(const float4*)(Vg + (size_t)(kb + r)*HD + (ch << 2));
            // K: B-operand of S = Q@K^T : slot (key/8)*8 + d/8
            uint32_t* dk = sKp + ((r >> 3)*8 + (ch >> 1))*KPAD + ((r & 7) << 3) + (ch & 1);
            dk[0] = __float_as_uint(kv.x);
            dk[2] = __float_as_uint(kv.y);
            dk[4] = __float_as_uint(kv.z);
            dk[6] = __float_as_uint(kv.w);
            // V: B-operand of P@V : slot (d/8)*4 + key/8
            uint32_t* dv = sVp + ((ch >> 1)*4 + (r >> 3))*KPAD
                              + ((ch & 1) << 5) + ((r & 3) << 1) + ((r >> 2) & 1);
            dv[0]  = __float_as_uint(vv.x);
            dv[8]  = __float_as_uint(vv.y);
            dv[16] = __float_as_uint(vv.z);
            dv[24] = __float_as_uint(vv.w);
        }
        __syncthreads();

        // S = Q @ K^T
        float s[4][4];
        #pragma unroll
        for (int i = 0; i < 4; i++)
            #pragma unroll
            for (int j = 0; j < 4; j++) s[i][j] = 0.f;
        #pragma unroll
        for (int ks = 0; ks < 8; ks++){
            #pragma unroll
            for (int nt = 0; nt < 4; nt++){
                uint2 b = *(const uint2*)(sKp + (nt*8 + ks)*KPAD + lane*2);
                uint32_t bf[2] = {b.x, b.y};
                mma_tf32(s[nt], qf[ks], bf);
            }
        }

        // scale + causal mask
        int qr0 = q0 + warp*16 + (lane >> 2);
        const float scale = 0.125f;
        #pragma unroll
        for (int nt = 0; nt < 4; nt++){
            int kc = kb + nt*8 + ((lane & 3) << 1);
            s[nt][0] = (kc     <= qr0    ) ? s[nt][0]*scale : -1e30f;
            s[nt][1] = (kc + 1 <= qr0    ) ? s[nt][1]*scale : -1e30f;
            s[nt][2] = (kc     <= qr0 + 8) ? s[nt][2]*scale : -1e30f;
            s[nt][3] = (kc + 1 <= qr0 + 8) ? s[nt][3]*scale : -1e30f;
        }

        // online softmax
        float rm0 = -1e30f, rm1 = -1e30f;
        #pragma unroll
        for (int nt = 0; nt < 4; nt++){
            rm0 = fmaxf(rm0, fmaxf(s[nt][0], s[nt][1]));
            rm1 = fmaxf(rm1, fmaxf(s[nt][2], s[nt][3]));
        }
        rm0 = fmaxf(rm0, __shfl_xor_sync(0xffffffffu, rm0, 1));
        rm0 = fmaxf(rm0, __shfl_xor_sync(0xffffffffu, rm0, 2));
        rm1 = fmaxf(rm1, __shfl_xor_sync(0xffffffffu, rm1, 1));
        rm1 = fmaxf(rm1, __shfl_xor_sync(0xffffffffu, rm1, 2));

        float mn0 = fmaxf(m0, rm0), mn1 = fmaxf(m1, rm1);
        float a0 = __expf(m0 - mn0), a1 = __expf(m1 - mn1);
        float rs0 = 0.f, rs1 = 0.f;
        #pragma unroll
        for (int nt = 0; nt < 4; nt++){
            s[nt][0] = __expf(s[nt][0] - mn0);
            s[nt][1] = __expf(s[nt][1] - mn0);
            s[nt][2] = __expf(s[nt][2] - mn1);
            s[nt][3] = __expf(s[nt][3] - mn1);
            rs0 += s[nt][0] + s[nt][1];
            rs1 += s[nt][2] + s[nt][3];
        }
        rs0 += __shfl_xor_sync(0xffffffffu, rs0, 1);
        rs0 += __shfl_xor_sync(0xffffffffu, rs0, 2);
        rs1 += __shfl_xor_sync(0xffffffffu, rs1, 1);
        rs1 += __shfl_xor_sync(0xffffffffu, rs1, 2);
        l0 = l0*a0 + rs0;
        l1 = l1*a1 + rs1;
        m0 = mn0; m1 = mn1;
        #pragma unroll
        for (int nt = 0; nt < 8; nt++){
            o[nt][0] *= a0; o[nt][1] *= a0;
            o[nt][2] *= a1; o[nt][3] *= a1;
        }

        // P (C-layout) -> permuted A-layout in this warp's private sQP slots
        {
            int lq = lane >> 2, lr = lane & 3;
            #pragma unroll
            for (int nt = 0; nt < 4; nt++){
                #pragma unroll
                for (int q = 0; q < 4; q++){
                    int cc = ((lr << 1) + (q & 1)) & 3;
                    int j  = (q >> 1) + ((lr >> 1) << 1);
                    sQP[(warp*8 + nt)*APAD + ((lq*4 + cc) << 2) + j] = f2tf(s[nt][q]);
                }
            }
        }
        __syncwarp();

        // O += P @ V
        #pragma unroll
        for (int ks = 0; ks < 4; ks++){
            uint4 at = *(const uint4*)(sQP + (warp*8 + ks)*APAD + lane*4);
            uint32_t af[4] = {at.x, at.y, at.z, at.w};
            #pragma unroll
            for (int nt = 0; nt < 8; nt++){
                uint2 b = *(const uint2*)(sVp + (nt*4 + ks)*KPAD + lane*2);
                uint32_t bf[2] = {b.x, b.y};
                mma_tf32(o[nt], af, bf);
            }
        }
        __syncwarp();   // P reads done before next iter's rewrite
    }

    // epilogue: O/l -> g_attn [b*T+t][h*64+d]
    float il0 = 1.0f / l0, il1 = 1.0f / l1;
    int b = bh >> 4, h = bh & 15;
    int t0 = q0 + warp*16 + (lane >> 2);
    #pragma unroll
    for (int nt = 0; nt < 8; nt++){
        int d = nt*8 + ((lane & 3) << 1);
        size_t base = ((size_t)(b*SEQ + t0))*DIMC + h*HD + d;
        *(float2*)(g_attn + base)                  = make_float2(o[nt][0]*il0, o[nt][1]*il0);
        *(float2*)(g_attn + base + (size_t)8*DIMC) = make_float2(o[nt][2]*il1, o[nt][3]*il1);
    }
}

// ---------------- launch ----------------------------------------------------
extern "C" void kernel_launch(void* const* d_in, const int* in_sizes, int n_in,
                              void* d_out, int out_size)
{
    const float* x  = (const float*)d_in[0];
    const float* wq = (const float*)d_in[1];
    const float* wk = (const float*)d_in[2];
    const float* wv = (const float*)d_in[3];
    const float* wo = (const float*)d_in[4];
    float* out = (float*)d_out;

    cudaFuncSetAttribute(gemm_tf32p, cudaFuncAttributeMaxDynamicSharedMemorySize, GSMEM);

    dim3 gq(DIMC/GTN, MTOT/GTM, 3);   // (8, 64, 3) fused QKV
    gemm_tf32p<<<gq, 256, GSMEM>>>(x, wq, wk, wv, nullptr, 1);
    attn_tf32<<<dim3(SEQ/QT, BATCH*NH), 128>>>();
    dim3 go(DIMC/GTN, MTOT/GTM, 1);
    gemm_tf32p<<<go, 256, GSMEM>>>(nullptr, wo, nullptr, nullptr, out, 0);
}

// round 7
// speedup vs baseline: 2.3612x; 2.3612x over previous
#include <cuda_runtime.h>
#include <cuda_fp16.h>
#include <cstdint>

#define DIMC  1024
#define NH    16
#define HD    64
#define BATCH 4
#define SEQ   2048
#define MTOT  (BATCH*SEQ)   // 8192

// ---------------- scratch (device globals; no allocation allowed) ----------
__device__ __half g_xh[(size_t)MTOT*DIMC];        // x in fp16
__device__ __half g_wh[(size_t)4*DIMC*DIMC];      // wq,wk,wv,wo in fp16
__device__ __half g_q[(size_t)MTOT*DIMC];         // [b*NH+h][t][d], pre-scaled by 1/8
__device__ __half g_k[(size_t)MTOT*DIMC];
__device__ __half g_v[(size_t)MTOT*DIMC];
__device__ __half g_attn[(size_t)MTOT*DIMC];      // [b*T+t][h*64+d]

// ---------------- helpers ---------------------------------------------------
__device__ __forceinline__ uint32_t smem_u32(const void* p){
    uint32_t a;
    asm("{ .reg .u64 t; cvta.to.shared.u64 t, %1; cvt.u32.u64 %0, t; }" : "=r"(a) : "l"(p));
    return a;
}
// pack two f32 -> f16x2 (lo, hi). PTX cvt f16x2: first source -> HIGH half.
__device__ __forceinline__ uint32_t packh2(float lo, float hi){
    uint32_t d;
    asm("cvt.rn.f16x2.f32 %0, %1, %2;" : "=r"(d) : "f"(hi), "f"(lo));
    return d;
}
__device__ __forceinline__ void cp16(uint32_t dst, const void* src){
    asm volatile("cp.async.cg.shared.global [%0], [%1], 16;" :: "r"(dst), "l"(src));
}
#define CP_COMMIT() asm volatile("cp.async.commit_group;" ::: "memory")
#define CP_WAIT(n)  asm volatile("cp.async.wait_group %0;" :: "n"(n) : "memory")

__device__ __forceinline__ void ldsm_x4(uint32_t& r0, uint32_t& r1, uint32_t& r2, uint32_t& r3,
                                        uint32_t addr){
    asm volatile("ldmatrix.sync.aligned.m8n8.x4.shared.b16 {%0,%1,%2,%3}, [%4];"
                 : "=r"(r0), "=r"(r1), "=r"(r2), "=r"(r3) : "r"(addr));
}
__device__ __forceinline__ void ldsm_x4t(uint32_t& r0, uint32_t& r1, uint32_t& r2, uint32_t& r3,
                                         uint32_t addr){
    asm volatile("ldmatrix.sync.aligned.m8n8.x4.trans.shared.b16 {%0,%1,%2,%3}, [%4];"
                 : "=r"(r0), "=r"(r1), "=r"(r2), "=r"(r3) : "r"(addr));
}
__device__ __forceinline__ void mma_f16(float c[4], const uint32_t a[4], const uint32_t b[2]){
    asm volatile(
        "mma.sync.aligned.m16n8k16.row.col.f32.f16.f16.f32 "
        "{%0,%1,%2,%3}, {%4,%5,%6,%7}, {%8,%9}, {%0,%1,%2,%3};"
        : "+f"(c[0]), "+f"(c[1]), "+f"(c[2]), "+f"(c[3])
        : "r"(a[0]), "r"(a[1]), "r"(a[2]), "r"(a[3]), "r"(b[0]), "r"(b[1]));
}

// ---------------- fp32 -> fp16 converts --------------------------------------
__global__ void cvt_x_f16(const float* __restrict__ src, int n8){
    int i = blockIdx.x*blockDim.x + threadIdx.x;
    if (i >= n8) return;
    float4 a = ((const float4*)src)[2*i];
    float4 b = ((const float4*)src)[2*i + 1];
    uint4 o;
    o.x = packh2(a.x, a.y); o.y = packh2(a.z, a.w);
    o.z = packh2(b.x, b.y); o.w = packh2(b.z, b.w);
    ((uint4*)g_xh)[i] = o;
}
// grid.y = 4 selects which weight
__global__ void cvt_w_f16(const float* __restrict__ w0, const float* __restrict__ w1,
                          const float* __restrict__ w2, const float* __restrict__ w3,
                          int n8){
    int i = blockIdx.x*blockDim.x + threadIdx.x;
    if (i >= n8) return;
    int z = blockIdx.y;
    const float* src = (z == 0) ? w0 : (z == 1) ? w1 : (z == 2) ? w2 : w3;
    __half* dst = g_wh + (size_t)z*DIMC*DIMC;
    float4 a = ((const float4*)src)[2*i];
    float4 b = ((const float4*)src)[2*i + 1];
    uint4 o;
    o.x = packh2(a.x, a.y); o.y = packh2(a.z, a.w);
    o.z = packh2(b.x, b.y); o.w = packh2(b.z, b.w);
    ((uint4*)dst)[i] = o;
}

// ============================================================================
// fp16 GEMM:  C[M,N] = A[M,K] @ W[N,K]^T   (both K-major fp16, K=1024)
// 128x128 tile, 4 warps (2x2), warp tile 64x64, BK=32, 3-stage cp.async,
// ldmatrix fragments, rows padded to 80 B (bank-clean for stride-20-word rows)
// ============================================================================
#define BM 128
#define BN 128
#define BK 32
#define GNT (DIMC/BK)       // 32
#define ROWH 40             // halves per smem row (80 B)
#define AST (BM*ROWH)       // halves per operand tile: 5120
#define STAGE_H (2*AST)     // 10240 halves = 20480 B
#define NSTG 3
#define GSMEM_BYTES (NSTG*STAGE_H*2)   // 61440

__device__ __forceinline__ void g_fill(uint32_t sbase, int st,
                                       const __half* __restrict__ A,
                                       const __half* __restrict__ W,
                                       int bm0, int bn0, int kt, int tid){
    uint32_t sd = sbase + (uint32_t)(st*STAGE_H*2);
    #pragma unroll
    for (int p = 0; p < 4; p++){
        int n = tid + p*128;          // 0..511
        int r = n >> 2, ch = n & 3;
        cp16(sd + (uint32_t)(r*80 + ch*16),
             A + (size_t)(bm0 + r)*DIMC + kt*BK + ch*8);
    }
    #pragma unroll
    for (int p = 0; p < 4; p++){
        int n = tid + p*128;
        int r = n >> 2, ch = n & 3;
        cp16(sd + (uint32_t)(AST*2 + r*80 + ch*16),
             W + (size_t)(bn0 + r)*DIMC + kt*BK + ch*8);
    }
}

__global__ void __launch_bounds__(128, 2)
gemm_f16(float* __restrict__ Cout, int qkv)
{
    extern __shared__ __align__(16) __half sm[];
    uint32_t sbase = smem_u32(sm);
    int tid = threadIdx.x, lane = tid & 31, warp = tid >> 5;
    int bm0 = blockIdx.y*BM, bn0 = blockIdx.x*BN;
    int z = qkv ? (int)blockIdx.z : 3;
    const __half* A = qkv ? g_xh : g_attn;
    const __half* W = g_wh + (size_t)z*DIMC*DIMC;
    int wm = (warp >> 1)*64, wn = (warp & 1)*64;

    float c[4][8][4];
    #pragma unroll
    for (int i = 0; i < 4; i++)
        #pragma unroll
        for (int j = 0; j < 8; j++)
            #pragma unroll
            for (int k = 0; k < 4; k++) c[i][j][k] = 0.f;

    g_fill(sbase, 0, A, W, bm0, bn0, 0, tid); CP_COMMIT();
    g_fill(sbase, 1, A, W, bm0, bn0, 1, tid); CP_COMMIT();

    for (int kt = 0; kt < GNT; kt++){
        int s = kt % 3;
        if (kt < GNT-1) { CP_WAIT(1); } else { CP_WAIT(0); }
        __syncthreads();
        if (kt + 2 < GNT){
            g_fill(sbase, (kt+2) % 3, A, W, bm0, bn0, kt+2, tid);
            CP_COMMIT();
        }

        uint32_t sa = sbase + (uint32_t)(s*STAGE_H*2);
        uint32_t sb = sa + (uint32_t)(AST*2);
        #pragma unroll
        for (int ks = 0; ks < 2; ks++){
            uint32_t af[4][4];
            #pragma unroll
            for (int mt = 0; mt < 4; mt++){
                int row = wm + mt*16 + (lane & 15);
                int col = ks*16 + ((lane & 16) ? 8 : 0);
                ldsm_x4(af[mt][0], af[mt][1], af[mt][2], af[mt][3],
                        sa + (uint32_t)(row*80 + col*2));
            }
            uint32_t bf[8][2];
            #pragma unroll
            for (int np = 0; np < 4; np++){
                int nr  = wn + np*16 + (lane & 7) + ((lane & 16) ? 8 : 0);
                int col = ks*16 + (lane & 8);
                uint32_t r0, r1, r2, r3;
                ldsm_x4(r0, r1, r2, r3, sb + (uint32_t)(nr*80 + col*2));
                bf[np*2][0]   = r0; bf[np*2][1]   = r1;
                bf[np*2+1][0] = r2; bf[np*2+1][1] = r3;
            }
            #pragma unroll
            for (int mt = 0; mt < 4; mt++)
                #pragma unroll
                for (int nt = 0; nt < 8; nt++)
                    mma_f16(c[mt][nt], af[mt], bf[nt]);
        }
    }

    // epilogue
    float sc = (qkv && z == 0) ? 0.125f : 1.0f;   // fold softmax scale into Q
    #pragma unroll
    for (int mt = 0; mt < 4; mt++){
        #pragma unroll
        for (int nt = 0; nt < 8; nt++){
            int gr = bm0 + wm + mt*16 + (lane >> 2);
            int gc = bn0 + wn + nt*8 + ((lane & 3) << 1);
            if (qkv){
                __half* dst = (z == 0) ? g_q : (z == 1) ? g_k : g_v;
                int bb = gr >> 11, tt = gr & (SEQ - 1);
                int hh = gc >> 6,  dd = gc & (HD - 1);
                size_t off = ((size_t)(bb*NH + hh)*SEQ + tt)*HD + dd;
                *(uint32_t*)(dst + off)         = packh2(c[mt][nt][0]*sc, c[mt][nt][1]*sc);
                *(uint32_t*)(dst + off + 8*HD)  = packh2(c[mt][nt][2]*sc, c[mt][nt][3]*sc);
            } else {
                *(float2*)(Cout + (size_t)gr*DIMC + gc)
                    = make_float2(c[mt][nt][0], c[mt][nt][1]);
                *(float2*)(Cout + (size_t)(gr + 8)*DIMC + gc)
                    = make_float2(c[mt][nt][2], c[mt][nt][3]);
            }
        }
    }
}

// ============================================================================
// causal flash attention: fp16 mma (m16n8k16), fp32 softmax, ldmatrix frags,
// register-only P re-fragmentation, 3-stage cp.async K/V pipeline.
// block = 128 thr (4 warps x 16 q-rows), QT=64, KTILE=32. rows padded to 144B.
// ============================================================================
#define QT 64
#define KTILE 32
#define ARH 72                 // halves per row (144 B)

__global__ void __launch_bounds__(128)
attn_f16()
{
    __shared__ __align__(16) __half sQ[QT*ARH];          //  9216 B
    __shared__ __align__(16) __half sK[3][KTILE*ARH];    // 13824 B
    __shared__ __align__(16) __half sV[3][KTILE*ARH];    // 13824 B

    int tid  = threadIdx.x;
    int lane = tid & 31;
    int warp = tid >> 5;
    int bh = blockIdx.y;
    int q0 = blockIdx.x * QT;

    const __half* Qg = g_q + (size_t)bh*SEQ*HD;
    const __half* Kg = g_k + (size_t)bh*SEQ*HD;
    const __half* Vg = g_v + (size_t)bh*SEQ*HD;

    uint32_t sQb = smem_u32(sQ);
    int nkt = (q0 + QT) / KTILE;   // >= 2 always

    // prologue: Q + KV stage 0 in group 0; KV stage 1 in group 1
    #pragma unroll
    for (int p = 0; p < 4; p++){
        int n = tid + p*128;           // 0..511
        int r = n >> 3, ch = n & 7;
        cp16(sQb + (uint32_t)(r*144 + ch*16), Qg + (size_t)(q0 + r)*HD + ch*8);
    }
    {
        uint32_t kb0 = smem_u32(sK[0]), vb0 = smem_u32(sV[0]);
        #pragma unroll
        for (int p = 0; p < 4; p++){
            int n = tid + p*128;
            int isV = n >> 8, m = n & 255;
            int r = m >> 3, ch = m & 7;
            cp16((isV ? vb0 : kb0) + (uint32_t)(r*144 + ch*16),
                 (isV ? Vg : Kg) + (size_t)r*HD + ch*8);
        }
    }
    CP_COMMIT();
    {
        uint32_t kb1 = smem_u32(sK[1]), vb1 = smem_u32(sV[1]);
        #pragma unroll
        for (int p = 0; p < 4; p++){
            int n = tid + p*128;
            int isV = n >> 8, m = n & 255;
            int r = m >> 3, ch = m & 7;
            cp16((isV ? vb1 : kb1) + (uint32_t)(r*144 + ch*16),
                 (isV ? Vg : Kg) + (size_t)(KTILE + r)*HD + ch*8);
        }
    }
    CP_COMMIT();

    uint32_t qf[4][4];
    float o[8][4];
    #pragma unroll
    for (int i = 0; i < 8; i++)
        #pragma unroll
        for (int j = 0; j < 4; j++) o[i][j] = 0.f;
    float m0 = -1e30f, m1 = -1e30f, l0 = 0.f, l1 = 0.f;

    for (int kt = 0; kt < nkt; kt++){
        int st = kt % 3;
        if (kt < nkt-1) { CP_WAIT(1); } else { CP_WAIT(0); }
        __syncthreads();
        if (kt + 2 < nkt){
            uint32_t kbn = smem_u32(sK[(kt+2)%3]), vbn = smem_u32(sV[(kt+2)%3]);
            int kb2 = (kt+2)*KTILE;
            #pragma unroll
            for (int p = 0; p < 4; p++){
                int n = tid + p*128;
                int isV = n >> 8, m = n & 255;
                int r = m >> 3, ch = m & 7;
                cp16((isV ? vbn : kbn) + (uint32_t)(r*144 + ch*16),
                     (isV ? Vg : Kg) + (size_t)(kb2 + r)*HD + ch*8);
            }
            CP_COMMIT();
        }
        if (kt == 0){
            // Q fragments (16 rows per warp, 4 k16-steps over Dh=64)
            #pragma unroll
            for (int ks = 0; ks < 4; ks++){
                int row = warp*16 + (lane & 15);
                int col = ks*16 + ((lane & 16) ? 8 : 0);
                ldsm_x4(qf[ks][0], qf[ks][1], qf[ks][2], qf[ks][3],
                        sQb + (uint32_t)(row*144 + col*2));
            }
        }

        int kb = kt*KTILE;
        int wrow0 = q0 + warp*16;
        if (kb <= wrow0 + 15){   // tile not fully masked for this warp
            uint32_t sKb = smem_u32(sK[st]);
            uint32_t sVb = smem_u32(sV[st]);

            // S = Q @ K^T  (16 q-rows x 32 keys), Q pre-scaled by 1/8
            float sv[4][4];
            #pragma unroll
            for (int i = 0; i < 4; i++)
                #pragma unroll
                for (int j = 0; j < 4; j++) sv[i][j] = 0.f;
            #pragma unroll
            for (int ks = 0; ks < 4; ks++){
                uint32_t kf[4][2];
                #pragma unroll
                for (int np = 0; np < 2; np++){
                    int nr  = np*16 + (lane & 7) + ((lane & 16) ? 8 : 0);
                    int col = ks*16 + (lane & 8);
                    uint32_t r0, r1, r2, r3;
                    ldsm_x4(r0, r1, r2, r3, sKb + (uint32_t)(nr*144 + col*2));
                    kf[np*2][0]   = r0; kf[np*2][1]   = r1;
                    kf[np*2+1][0] = r2; kf[np*2+1][1] = r3;
                }
                #pragma unroll
                for (int nt = 0; nt < 4; nt++)
                    mma_f16(sv[nt], qf[ks], kf[nt]);
            }

            // causal mask (skip when the whole tile is visible to this warp)
            int qr0 = wrow0 + (lane >> 2);
            if (kb + KTILE - 1 > wrow0){
                #pragma unroll
                for (int nt = 0; nt < 4; nt++){
                    int kc = kb + nt*8 + ((lane & 3) << 1);
                    if (kc     > qr0    ) sv[nt][0] = -1e30f;
                    if (kc + 1 > qr0    ) sv[nt][1] = -1e30f;
                    if (kc     > qr0 + 8) sv[nt][2] = -1e30f;
                    if (kc + 1 > qr0 + 8) sv[nt][3] = -1e30f;
                }
            }

            // online softmax (rows qr0 and qr0+8, per lane-quad)
            float rm0 = -1e30f, rm1 = -1e30f;
            #pragma unroll
            for (int nt = 0; nt < 4; nt++){
                rm0 = fmaxf(rm0, fmaxf(sv[nt][0], sv[nt][1]));
                rm1 = fmaxf(rm1, fmaxf(sv[nt][2], sv[nt][3]));
            }
            rm0 = fmaxf(rm0, __shfl_xor_sync(0xffffffffu, rm0, 1));
            rm0 = fmaxf(rm0, __shfl_xor_sync(0xffffffffu, rm0, 2));
            rm1 = fmaxf(rm1, __shfl_xor_sync(0xffffffffu, rm1, 1));
            rm1 = fmaxf(rm1, __shfl_xor_sync(0xffffffffu, rm1, 2));

            float mn0 = fmaxf(m0, rm0), mn1 = fmaxf(m1, rm1);
            float a0 = __expf(m0 - mn0), a1 = __expf(m1 - mn1);
            float rs0 = 0.f, rs1 = 0.f;
            #pragma unroll
            for (int nt = 0; nt < 4; nt++){
                sv[nt][0] = __expf(sv[nt][0] - mn0);
                sv[nt][1] = __expf(sv[nt][1] - mn0);
                sv[nt][2] = __expf(sv[nt][2] - mn1);
                sv[nt][3] = __expf(sv[nt][3] - mn1);
                rs0 += sv[nt][0] + sv[nt][1];
                rs1 += sv[nt][2] + sv[nt][3];
            }
            rs0 += __shfl_xor_sync(0xffffffffu, rs0, 1);
            rs0 += __shfl_xor_sync(0xffffffffu, rs0, 2);
            rs1 += __shfl_xor_sync(0xffffffffu, rs1, 1);
            rs1 += __shfl_xor_sync(0xffffffffu, rs1, 2);
            l0 = l0*a0 + rs0;
            l1 = l1*a1 + rs1;
            m0 = mn0; m1 = mn1;
            #pragma unroll
            for (int nt = 0; nt < 8; nt++){
                o[nt][0] *= a0; o[nt][1] *= a0;
                o[nt][2] *= a1; o[nt][3] *= a1;
            }

            // P: C-fragment -> A-fragment entirely in registers
            uint32_t pf[2][4];
            #pragma unroll
            for (int j = 0; j < 2; j++){
                pf[j][0] = packh2(sv[2*j][0],   sv[2*j][1]);
                pf[j][1] = packh2(sv[2*j][2],   sv[2*j][3]);
                pf[j][2] = packh2(sv[2*j+1][0], sv[2*j+1][1]);
                pf[j][3] = packh2(sv[2*j+1][2], sv[2*j+1][3]);
            }

            // O += P @ V  (V fragments via ldmatrix.trans)
            #pragma unroll
            for (int j = 0; j < 2; j++){
                uint32_t vf[8][2];
                #pragma unroll
                for (int np = 0; np < 4; np++){
                    int kr = 16*j + (lane & 7) + ((lane & 8) ? 8 : 0);
                    int dc = (np*2 + ((lane & 16) ? 1 : 0)) * 8;
                    uint32_t r0, r1, r2, r3;
                    ldsm_x4t(r0, r1, r2, r3, sVb + (uint32_t)(kr*144 + dc*2));
                    vf[np*2][0]   = r0; vf[np*2][1]   = r1;
                    vf[np*2+1][0] = r2; vf[np*2+1][1] = r3;
                }
                #pragma unroll
                for (int nt = 0; nt < 8; nt++)
                    mma_f16(o[nt], pf[j], vf[nt]);
            }
        }
    }

    // epilogue: O/l -> g_attn (fp16) [b*T+t][h*64+d]
    float il0 = 1.0f / l0, il1 = 1.0f / l1;
    int b = bh >> 4, h = bh & 15;
    int t0 = q0 + warp*16 + (lane >> 2);
    #pragma unroll
    for (int nt = 0; nt < 8; nt++){
        int d = nt*8 + ((lane & 3) << 1);
        size_t base = ((size_t)(b*SEQ + t0))*DIMC + h*HD + d;
        *(uint32_t*)(g_attn + base)                  = packh2(o[nt][0]*il0, o[nt][1]*il0);
        *(uint32_t*)(g_attn + base + (size_t)8*DIMC) = packh2(o[nt][2]*il1, o[nt][3]*il1);
    }
}

// ---------------- launch ----------------------------------------------------
extern "C" void kernel_launch(void* const* d_in, const int* in_sizes, int n_in,
                              void* d_out, int out_size)
{
    const float* x  = (const float*)d_in[0];
    const float* wq = (const float*)d_in[1];
    const float* wk = (const float*)d_in[2];
    const float* wv = (const float*)d_in[3];
    const float* wo = (const float*)d_in[4];
    float* out = (float*)d_out;

    cudaFuncSetAttribute(gemm_f16, cudaFuncAttributeMaxDynamicSharedMemorySize, GSMEM_BYTES);

    // fp32 -> fp16 converts
    int n8x = MTOT*DIMC/8;     // 1048576
    int n8w = DIMC*DIMC/8;     // 131072
    cvt_x_f16<<<(n8x+255)/256, 256>>>(x, n8x);
    cvt_w_f16<<<dim3((n8w+255)/256, 4), 256>>>(wq, wk, wv, wo, n8w);

    dim3 gq(DIMC/BN, MTOT/BM, 3);   // fused QKV
    gemm_f16<<<gq, 128, GSMEM_BYTES>>>(nullptr, 1);
    attn_f16<<<dim3(SEQ/QT, BATCH*NH), 128>>>();
    dim3 go(DIMC/BN, MTOT/BM, 1);
    gemm_f16<<<go, 128, GSMEM_BYTES>>>(out, 0);
}

// round 9
// speedup vs baseline: 2.3947x; 1.0142x over previous
#include <cuda_runtime.h>
#include <cuda_fp16.h>
#include <cstdint>

#define DIMC  1024
#define NH    16
#define HD    64
#define BATCH 4
#define SEQ   2048
#define MTOT  (BATCH*SEQ)   // 8192

// ---------------- scratch (device globals; no allocation allowed) ----------
__device__ __half g_xh[(size_t)MTOT*DIMC];        // x in fp16
__device__ __half g_wh[(size_t)4*DIMC*DIMC];      // wq,wk,wv,wo in fp16
__device__ __half g_q[(size_t)MTOT*DIMC];         // [b*NH+h][t][d], pre-scaled by log2e/8
__device__ __half g_k[(size_t)MTOT*DIMC];
__device__ __half g_v[(size_t)MTOT*DIMC];
__device__ __half g_attn[(size_t)MTOT*DIMC];      // [b*T+t][h*64+d]

// ---------------- helpers ---------------------------------------------------
__device__ __forceinline__ uint32_t smem_u32(const void* p){
    uint32_t a;
    asm("{ .reg .u64 t; cvta.to.shared.u64 t, %1; cvt.u32.u64 %0, t; }" : "=r"(a) : "l"(p));
    return a;
}
// pack two f32 -> f16x2 (lo, hi). PTX cvt f16x2: first source -> HIGH half.
__device__ __forceinline__ uint32_t packh2(float lo, float hi){
    uint32_t d;
    asm("cvt.rn.f16x2.f32 %0, %1, %2;" : "=r"(d) : "f"(hi), "f"(lo));
    return d;
}
__device__ __forceinline__ float ex2(float x){
    float r; asm("ex2.approx.f32 %0, %1;" : "=f"(r) : "f"(x)); return r;
}
__device__ __forceinline__ void cp16(uint32_t dst, const void* src){
    asm volatile("cp.async.cg.shared.global [%0], [%1], 16;" :: "r"(dst), "l"(src));
}
#define CP_COMMIT() asm volatile("cp.async.commit_group;" ::: "memory")
#define CP_WAIT(n)  asm volatile("cp.async.wait_group %0;" :: "n"(n) : "memory")

__device__ __forceinline__ void ldsm_x4(uint32_t& r0, uint32_t& r1, uint32_t& r2, uint32_t& r3,
                                        uint32_t addr){
    asm volatile("ldmatrix.sync.aligned.m8n8.x4.shared.b16 {%0,%1,%2,%3}, [%4];"
                 : "=r"(r0), "=r"(r1), "=r"(r2), "=r"(r3) : "r"(addr));
}
__device__ __forceinline__ void ldsm_x4t(uint32_t& r0, uint32_t& r1, uint32_t& r2, uint32_t& r3,
                                         uint32_t addr){
    asm volatile("ldmatrix.sync.aligned.m8n8.x4.trans.shared.b16 {%0,%1,%2,%3}, [%4];"
                 : "=r"(r0), "=r"(r1), "=r"(r2), "=r"(r3) : "r"(addr));
}
__device__ __forceinline__ void mma_f16(float c[4], const uint32_t a[4], const uint32_t b[2]){
    asm volatile(
        "mma.sync.aligned.m16n8k16.row.col.f32.f16.f16.f32 "
        "{%0,%1,%2,%3}, {%4,%5,%6,%7}, {%8,%9}, {%0,%1,%2,%3};"
        : "+f"(c[0]), "+f"(c[1]), "+f"(c[2]), "+f"(c[3])
        : "r"(a[0]), "r"(a[1]), "r"(a[2]), "r"(a[3]), "r"(b[0]), "r"(b[1]));
}

// ---------------- fp32 -> fp16 converts --------------------------------------
__global__ void cvt_x_f16(const float* __restrict__ src, int n8){
    int i = blockIdx.x*blockDim.x + threadIdx.x;
    if (i >= n8) return;
    float4 a = ((const float4*)src)[2*i];
    float4 b = ((const float4*)src)[2*i + 1];
    uint4 o;
    o.x = packh2(a.x, a.y); o.y = packh2(a.z, a.w);
    o.z = packh2(b.x, b.y); o.w = packh2(b.z, b.w);
    ((uint4*)g_xh)[i] = o;
}
__global__ void cvt_w_f16(const float* __restrict__ w0, const float* __restrict__ w1,
                          const float* __restrict__ w2, const float* __restrict__ w3,
                          int n8){
    int i = blockIdx.x*blockDim.x + threadIdx.x;
    if (i >= n8) return;
    int z = blockIdx.y;
    const float* src = (z == 0) ? w0 : (z == 1) ? w1 : (z == 2) ? w2 : w3;
    __half* dst = g_wh + (size_t)z*DIMC*DIMC;
    float4 a = ((const float4*)src)[2*i];
    float4 b = ((const float4*)src)[2*i + 1];
    uint4 o;
    o.x = packh2(a.x, a.y); o.y = packh2(a.z, a.w);
    o.z = packh2(b.x, b.y); o.w = packh2(b.z, b.w);
    ((uint4*)dst)[i] = o;
}

// ============================================================================
// fp16 GEMM:  C[M,N] = A[M,K] @ W[N,K]^T   (both K-major fp16, K=1024)
// 128x128 tile, 4 warps (2x2), warp tile 64x64, BK=32, 3-stage cp.async,
// ldmatrix fragments, rows padded to 80 B. 3 CTAs/SM.
// ============================================================================
#define BM 128
#define BN 128
#define BK 32
#define GNT (DIMC/BK)       // 32
#define ROWH 40             // halves per smem row (80 B)
#define AST (BM*ROWH)       // halves per operand tile: 5120
#define STAGE_H (2*AST)     // 10240 halves = 20480 B
#define NSTG 3
#define GSMEM_BYTES (NSTG*STAGE_H*2)   // 61440

__device__ __forceinline__ void g_fill(uint32_t sbase, int st,
                                       const __half* __restrict__ A,
                                       const __half* __restrict__ W,
                                       int bm0, int bn0, int kt, int tid){
    uint32_t sd = sbase + (uint32_t)(st*STAGE_H*2);
    #pragma unroll
    for (int p = 0; p < 4; p++){
        int n = tid + p*128;          // 0..511
        int r = n >> 2, ch = n & 3;
        cp16(sd + (uint32_t)(r*80 + ch*16),
             A + (size_t)(bm0 + r)*DIMC + kt*BK + ch*8);
    }
    #pragma unroll
    for (int p = 0; p < 4; p++){
        int n = tid + p*128;
        int r = n >> 2, ch = n & 3;
        cp16(sd + (uint32_t)(AST*2 + r*80 + ch*16),
             W + (size_t)(bn0 + r)*DIMC + kt*BK + ch*8);
    }
}

__global__ void __launch_bounds__(128, 3)
gemm_f16(float* __restrict__ Cout, int qkv)
{
    extern __shared__ __align__(16) __half sm[];
    uint32_t sbase = smem_u32(sm);
    int tid = threadIdx.x, lane = tid & 31, warp = tid >> 5;
    int bm0 = blockIdx.y*BM, bn0 = blockIdx.x*BN;
    int z = qkv ? (int)blockIdx.z : 3;
    const __half* A = qkv ? g_xh : g_attn;
    const __half* W = g_wh + (size_t)z*DIMC*DIMC;
    int wm = (warp >> 1)*64, wn = (warp & 1)*64;

    // per-lane ldmatrix byte offsets (hoisted out of the hot loop)
    uint32_t aOff = (uint32_t)((wm + (lane & 15))*80 + ((lane & 16) ? 16 : 0));
    uint32_t bOff = (uint32_t)(AST*2 + (wn + (lane & 7) + ((lane & 16) ? 8 : 0))*80
                               + ((lane & 8) << 1));

    float c[4][8][4];
    #pragma unroll
    for (int i = 0; i < 4; i++)
        #pragma unroll
        for (int j = 0; j < 8; j++)
            #pragma unroll
            for (int k = 0; k < 4; k++) c[i][j][k] = 0.f;

    g_fill(sbase, 0, A, W, bm0, bn0, 0, tid); CP_COMMIT();
    g_fill(sbase, 1, A, W, bm0, bn0, 1, tid); CP_COMMIT();

    for (int kt = 0; kt < GNT; kt++){
        int s = kt % 3;
        if (kt < GNT-1) { CP_WAIT(1); } else { CP_WAIT(0); }
        __syncthreads();
        if (kt + 2 < GNT){
            g_fill(sbase, (kt+2) % 3, A, W, bm0, bn0, kt+2, tid);
            CP_COMMIT();
        }

        uint32_t sa = sbase + (uint32_t)(s*STAGE_H*2);
        #pragma unroll
        for (int ks = 0; ks < 2; ks++){
            uint32_t af[4][4];
            #pragma unroll
            for (int mt = 0; mt < 4; mt++)
                ldsm_x4(af[mt][0], af[mt][1], af[mt][2], af[mt][3],
                        sa + aOff + (uint32_t)(mt*1280 + ks*32));
            uint32_t bf[8][2];
            #pragma unroll
            for (int np = 0; np < 4; np++){
                uint32_t r0, r1, r2, r3;
                ldsm_x4(r0, r1, r2, r3, sa + bOff + (uint32_t)(np*1280 + ks*32));
                bf[np*2][0]   = r0; bf[np*2][1]   = r1;
                bf[np*2+1][0] = r2; bf[np*2+1][1] = r3;
            }
            #pragma unroll
            for (int mt = 0; mt < 4; mt++)
                #pragma unroll
                for (int nt = 0; nt < 8; nt++)
                    mma_f16(c[mt][nt], af[mt], bf[nt]);
        }
    }

    // epilogue. Q gets softmax scale + log2e folded in (exp2-domain softmax).
    float sc = (qkv && z == 0) ? 0.125f*1.44269504088896f : 1.0f;
    #pragma unroll
    for (int mt = 0; mt < 4; mt++){
        #pragma unroll
        for (int nt = 0; nt < 8; nt++){
            int gr = bm0 + wm + mt*16 + (lane >> 2);
            int gc = bn0 + wn + nt*8 + ((lane & 3) << 1);
            if (qkv){
                __half* dst = (z == 0) ? g_q : (z == 1) ? g_k : g_v;
                int bb = gr >> 11, tt = gr & (SEQ - 1);
                int hh = gc >> 6,  dd = gc & (HD - 1);
                size_t off = ((size_t)(bb*NH + hh)*SEQ + tt)*HD + dd;
                *(uint32_t*)(dst + off)         = packh2(c[mt][nt][0]*sc, c[mt][nt][1]*sc);
                *(uint32_t*)(dst + off + 8*HD)  = packh2(c[mt][nt][2]*sc, c[mt][nt][3]*sc);
            } else {
                *(float2*)(Cout + (size_t)gr*DIMC + gc)
                    = make_float2(c[mt][nt][0], c[mt][nt][1]);
                *(float2*)(Cout + (size_t)(gr + 8)*DIMC + gc)
                    = make_float2(c[mt][nt][2], c[mt][nt][3]);
            }
        }
    }
}

// ============================================================================
// causal flash attention: fp16 mma (m16n8k16), exp2-domain fp32 softmax,
// ldmatrix frags, register-only P re-frag, 3-stage cp.async K/V pipeline.
// block = 128 thr (4 warps x 16 q-rows), QT=64, KTILE=32, rows 144 B.
// q-tiles assigned in REVERSE order (longest CTAs first) for wave balance.
// ============================================================================
#define QT 64
#define KTILE 32
#define ARH 72                 // halves per row (144 B)
#define KVSTRIDE (KTILE*ARH*2) // 9216 B per K (or V) stage

__global__ void __launch_bounds__(128, 4)
attn_f16()
{
    __shared__ __align__(16) __half sQ[QT*ARH];          //  9216 B
    __shared__ __align__(16) __half sK[3][KTILE*ARH];    // 13824 B
    __shared__ __align__(16) __half sV[3][KTILE*ARH];    // 13824 B

    int tid  = threadIdx.x;
    int lane = tid & 31;
    int warp = tid >> 5;
    int bh = blockIdx.y;
    int q0 = ((int)gridDim.x - 1 - (int)blockIdx.x) * QT;   // longest first

    const __half* Qg = g_q + (size_t)bh*SEQ*HD;
    const __half* Kg = g_k + (size_t)bh*SEQ*HD;
    const __half* Vg = g_v + (size_t)bh*SEQ*HD;

    uint32_t sQb = smem_u32(sQ);
    uint32_t sK0 = smem_u32(sK[0]);
    uint32_t sV0 = smem_u32(sV[0]);
    int nkt = (q0 + QT) / KTILE;   // >= 2 always

    // per-lane ldmatrix byte offsets (loop-invariant)
    uint32_t kOff = (uint32_t)(((lane & 7) + ((lane & 16) ? 8 : 0))*144 + ((lane & 8) << 1));
    uint32_t vOff = (uint32_t)(((lane & 7) + ((lane & 8) ? 8 : 0))*144 + ((lane & 16) ? 16 : 0));

    // prologue: Q + KV stage 0 in group 0; KV stage 1 in group 1
    #pragma unroll
    for (int p = 0; p < 4; p++){
        int n = tid + p*128;           // 0..511
        int r = n >> 3, ch = n & 7;
        cp16(sQb + (uint32_t)(r*144 + ch*16), Qg + (size_t)(q0 + r)*HD + ch*8);
    }
    #pragma unroll
    for (int p = 0; p < 4; p++){
        int n = tid + p*128;
        int isV = n >> 8, m = n & 255;
        int r = m >> 3, ch = m & 7;
        cp16((isV ? sV0 : sK0) + (uint32_t)(r*144 + ch*16),
             (isV ? Vg : Kg) + (size_t)r*HD + ch*8);
    }
    CP_COMMIT();
    #pragma unroll
    for (int p = 0; p < 4; p++){
        int n = tid + p*128;
        int isV = n >> 8, m = n & 255;
        int r = m >> 3, ch = m & 7;
        cp16((isV ? sV0 : sK0) + (uint32_t)(KVSTRIDE + r*144 + ch*16),
             (isV ? Vg : Kg) + (size_t)(KTILE + r)*HD + ch*8);
    }
    CP_COMMIT();

    uint32_t qf[4][4];
    float o[8][4];
    #pragma unroll
    for (int i = 0; i < 8; i++)
        #pragma unroll
        for (int j = 0; j < 4; j++) o[i][j] = 0.f;
    float m0 = -1e30f, m1 = -1e30f, l0 = 0.f, l1 = 0.f;

    uint32_t stOff = 0;           // rotating stage byte-offset (0, 9216, 18432)
    for (int kt = 0; kt < nkt; kt++){
        if (kt < nkt-1) { CP_WAIT(1); } else { CP_WAIT(0); }
        __syncthreads();
        if (kt + 2 < nkt){
            uint32_t nOff = stOff + 2u*KVSTRIDE;
            if (nOff >= 3u*KVSTRIDE) nOff -= 3u*KVSTRIDE;
            int kb2 = (kt+2)*KTILE;
            #pragma unroll
            for (int p = 0; p < 4; p++){
                int n = tid + p*128;
                int isV = n >> 8, m = n & 255;
                int r = m >> 3, ch = m & 7;
                cp16((isV ? sV0 : sK0) + nOff + (uint32_t)(r*144 + ch*16),
                     (isV ? Vg : Kg) + (size_t)(kb2 + r)*HD + ch*8);
            }
            CP_COMMIT();
        }
        if (kt == 0){
            #pragma unroll
            for (int ks = 0; ks < 4; ks++){
                int row = warp*16 + (lane & 15);
                int col = ks*16 + ((lane & 16) ? 8 : 0);
                ldsm_x4(qf[ks][0], qf[ks][1], qf[ks][2], qf[ks][3],
                        sQb + (uint32_t)(row*144 + col*2));
            }
        }

        int kb = kt*KTILE;
        int wrow0 = q0 + warp*16;
        if (kb <= wrow0 + 15){   // tile not fully masked for this warp
            uint32_t sKb = sK0 + stOff;
            uint32_t sVb = sV0 + stOff;

            // S = Q @ K^T  (16 q-rows x 32 keys); Q pre-scaled by log2e/8
            float sv[4][4];
            #pragma unroll
            for (int i = 0; i < 4; i++)
                #pragma unroll
                for (int j = 0; j < 4; j++) sv[i][j] = 0.f;
            #pragma unroll
            for (int ks = 0; ks < 4; ks++){
                uint32_t kf[4][2];
                #pragma unroll
                for (int np = 0; np < 2; np++){
                    uint32_t r0, r1, r2, r3;
                    ldsm_x4(r0, r1, r2, r3, sKb + kOff + (uint32_t)(np*2304 + ks*32));
                    kf[np*2][0]   = r0; kf[np*2][1]   = r1;
                    kf[np*2+1][0] = r2; kf[np*2+1][1] = r3;
                }
                #pragma unroll
                for (int nt = 0; nt < 4; nt++)
                    mma_f16(sv[nt], qf[ks], kf[nt]);
            }

            // causal mask (diagonal tiles only)
            int qr0 = wrow0 + (lane >> 2);
            if (kb + KTILE - 1 > wrow0){
                #pragma unroll
                for (int nt = 0; nt < 4; nt++){
                    int kc = kb + nt*8 + ((lane & 3) << 1);
                    if (kc     > qr0    ) sv[nt][0] = -1e30f;
                    if (kc + 1 > qr0    ) sv[nt][1] = -1e30f;
                    if (kc     > qr0 + 8) sv[nt][2] = -1e30f;
                    if (kc + 1 > qr0 + 8) sv[nt][3] = -1e30f;
                }
            }

            // online softmax in exp2 domain (rows qr0 and qr0+8 per lane-quad)
            float rm0 = -1e30f, rm1 = -1e30f;
            #pragma unroll
            for (int nt = 0; nt < 4; nt++){
                rm0 = fmaxf(rm0, fmaxf(sv[nt][0], sv[nt][1]));
                rm1 = fmaxf(rm1, fmaxf(sv[nt][2], sv[nt][3]));
            }
            rm0 = fmaxf(rm0, __shfl_xor_sync(0xffffffffu, rm0, 1));
            rm0 = fmaxf(rm0, __shfl_xor_sync(0xffffffffu, rm0, 2));
            rm1 = fmaxf(rm1, __shfl_xor_sync(0xffffffffu, rm1, 1));
            rm1 = fmaxf(rm1, __shfl_xor_sync(0xffffffffu, rm1, 2));

            float mn0 = fmaxf(m0, rm0), mn1 = fmaxf(m1, rm1);
            float a0 = ex2(m0 - mn0), a1 = ex2(m1 - mn1);
            float rs0 = 0.f, rs1 = 0.f;
            #pragma unroll
            for (int nt = 0; nt < 4; nt++){
                sv[nt][0] = ex2(sv[nt][0] - mn0);
                sv[nt][1] = ex2(sv[nt][1] - mn0);
                sv[nt][2] = ex2(sv[nt][2] - mn1);
                sv[nt][3] = ex2(sv[nt][3] - mn1);
                rs0 += sv[nt][0] + sv[nt][1];
                rs1 += sv[nt][2] + sv[nt][3];
            }
            rs0 += __shfl_xor_sync(0xffffffffu, rs0, 1);
            rs0 += __shfl_xor_sync(0xffffffffu, rs0, 2);
            rs1 += __shfl_xor_sync(0xffffffffu, rs1, 1);
            rs1 += __shfl_xor_sync(0xffffffffu, rs1, 2);
            l0 = l0*a0 + rs0;
            l1 = l1*a1 + rs1;
            m0 = mn0; m1 = mn1;
            #pragma unroll
            for (int nt = 0; nt < 8; nt++){
                o[nt][0] *= a0; o[nt][1] *= a0;
                o[nt][2] *= a1; o[nt][3] *= a1;
            }

            // P: C-fragment -> A-fragment entirely in registers
            uint32_t pf[2][4];
            #pragma unroll
            for (int j = 0; j < 2; j++){
                pf[j][0] = packh2(sv[2*j][0],   sv[2*j][1]);
                pf[j][1] = packh2(sv[2*j][2],   sv[2*j][3]);
                pf[j][2] = packh2(sv[2*j+1][0], sv[2*j+1][1]);
                pf[j][3] = packh2(sv[2*j+1][2], sv[2*j+1][3]);
            }

            // O += P @ V  (V fragments via ldmatrix.trans)
            #pragma unroll
            for (int j = 0; j < 2; j++){
                uint32_t vf[8][2];
                #pragma unroll
                for (int np = 0; np < 4; np++){
                    uint32_t r0, r1, r2, r3;
                    ldsm_x4t(r0, r1, r2, r3, sVb + vOff + (uint32_t)(j*2304 + np*32));
                    vf[np*2][0]   = r0; vf[np*2][1]   = r1;
                    vf[np*2+1][0] = r2; vf[np*2+1][1] = r3;
                }
                #pragma unroll
                for (int nt = 0; nt < 8; nt++)
                    mma_f16(o[nt], pf[j], vf[nt]);
            }
        }
        stOff += KVSTRIDE;
        if (stOff >= 3u*KVSTRIDE) stOff = 0;
    }

    // epilogue: O/l -> g_attn (fp16) [b*T+t][h*64+d]
    float il0 = 1.0f / l0, il1 = 1.0f / l1;
    int b = bh >> 4, h = bh & 15;
    int t0 = q0 + warp*16 + (lane >> 2);
    #pragma unroll
    for (int nt = 0; nt < 8; nt++){
        int d = nt*8 + ((lane & 3) << 1);
        size_t base = ((size_t)(b*SEQ + t0))*DIMC + h*HD + d;
        *(uint32_t*)(g_attn + base)                  = packh2(o[nt][0]*il0, o[nt][1]*il0);
        *(uint32_t*)(g_attn + base + (size_t)8*DIMC) = packh2(o[nt][2]*il1, o[nt][3]*il1);
    }
}

// ---------------- launch ----------------------------------------------------
extern "C" void kernel_launch(void* const* d_in, const int* in_sizes, int n_in,
                              void* d_out, int out_size)
{
    const float* x  = (const float*)d_in[0];
    const float* wq = (const float*)d_in[1];
    const float* wk = (const float*)d_in[2];
    const float* wv = (const float*)d_in[3];
    const float* wo = (const float*)d_in[4];
    float* out = (float*)d_out;

    cudaFuncSetAttribute(gemm_f16, cudaFuncAttributeMaxDynamicSharedMemorySize, GSMEM_BYTES);

    // fp32 -> fp16 converts
    int n8x = MTOT*DIMC/8;     // 1048576
    int n8w = DIMC*DIMC/8;     // 131072
    cvt_x_f16<<<(n8x+255)/256, 256>>>(x, n8x);
    cvt_w_f16<<<dim3((n8w+255)/256, 4), 256>>>(wq, wk, wv, wo, n8w);

    dim3 gq(DIMC/BN, MTOT/BM, 3);   // fused QKV
    gemm_f16<<<gq, 128, GSMEM_BYTES>>>(nullptr, 1);
    attn_f16<<<dim3(SEQ/QT, BATCH*NH), 128>>>();
    dim3 go(DIMC/BN, MTOT/BM, 1);
    gemm_f16<<<go, 128, GSMEM_BYTES>>>(out, 0);
}

// round 10
// speedup vs baseline: 2.5704x; 1.0734x over previous
#include <cuda_runtime.h>
#include <cuda_fp16.h>
#include <cstdint>

#define DIMC  1024
#define NH    16
#define HD    64
#define BATCH 4
#define SEQ   2048
#define MTOT  (BATCH*SEQ)   // 8192

// ---------------- scratch (device globals; no allocation allowed) ----------
__device__ __half g_xh[(size_t)MTOT*DIMC];        // x in fp16
__device__ __half g_wh[(size_t)4*DIMC*DIMC];      // wq,wk,wv,wo in fp16
__device__ __half g_q[(size_t)MTOT*DIMC];         // [b*NH+h][t][d], pre-scaled by log2e/8
__device__ __half g_k[(size_t)MTOT*DIMC];
__device__ __half g_v[(size_t)MTOT*DIMC];
__device__ __half g_attn[(size_t)MTOT*DIMC];      // [b*T+t][h*64+d]

// ---------------- helpers ---------------------------------------------------
__device__ __forceinline__ uint32_t smem_u32(const void* p){
    uint32_t a;
    asm("{ .reg .u64 t; cvta.to.shared.u64 t, %1; cvt.u32.u64 %0, t; }" : "=r"(a) : "l"(p));
    return a;
}
// pack two f32 -> f16x2 (lo, hi). PTX cvt f16x2: first source -> HIGH half.
__device__ __forceinline__ uint32_t packh2(float lo, float hi){
    uint32_t d;
    asm("cvt.rn.f16x2.f32 %0, %1, %2;" : "=r"(d) : "f"(hi), "f"(lo));
    return d;
}
__device__ __forceinline__ float ex2(float x){
    float r; asm("ex2.approx.f32 %0, %1;" : "=f"(r) : "f"(x)); return r;
}
__device__ __forceinline__ uint32_t ex2h2(uint32_t x){
    uint32_t r; asm("ex2.approx.f16x2 %0, %1;" : "=r"(r) : "r"(x)); return r;
}
__device__ __forceinline__ uint32_t hadd2(uint32_t a, uint32_t b){
    uint32_t r; asm("add.rn.f16x2 %0, %1, %2;" : "=r"(r) : "r"(a), "r"(b)); return r;
}
__device__ __forceinline__ float2 h2f2(uint32_t h){
    float2 f;
    asm("{ .reg .f16 lo, hi;\n\t mov.b32 {lo, hi}, %2;\n\t"
        "cvt.f32.f16 %0, lo;\n\t cvt.f32.f16 %1, hi; }"
        : "=f"(f.x), "=f"(f.y) : "r"(h));
    return f;
}
__device__ __forceinline__ void cp16(uint32_t dst, const void* src){
    asm volatile("cp.async.cg.shared.global [%0], [%1], 16;" :: "r"(dst), "l"(src));
}
#define CP_COMMIT() asm volatile("cp.async.commit_group;" ::: "memory")
#define CP_WAIT(n)  asm volatile("cp.async.wait_group %0;" :: "n"(n) : "memory")

__device__ __forceinline__ void ldsm_x4(uint32_t& r0, uint32_t& r1, uint32_t& r2, uint32_t& r3,
                                        uint32_t addr){
    asm volatile("ldmatrix.sync.aligned.m8n8.x4.shared.b16 {%0,%1,%2,%3}, [%4];"
                 : "=r"(r0), "=r"(r1), "=r"(r2), "=r"(r3) : "r"(addr));
}
__device__ __forceinline__ void ldsm_x4t(uint32_t& r0, uint32_t& r1, uint32_t& r2, uint32_t& r3,
                                         uint32_t addr){
    asm volatile("ldmatrix.sync.aligned.m8n8.x4.trans.shared.b16 {%0,%1,%2,%3}, [%4];"
                 : "=r"(r0), "=r"(r1), "=r"(r2), "=r"(r3) : "r"(addr));
}
__device__ __forceinline__ void mma_f16(float c[4], const uint32_t a[4], const uint32_t b[2]){
    asm volatile(
        "mma.sync.aligned.m16n8k16.row.col.f32.f16.f16.f32 "
        "{%0,%1,%2,%3}, {%4,%5,%6,%7}, {%8,%9}, {%0,%1,%2,%3};"
        : "+f"(c[0]), "+f"(c[1]), "+f"(c[2]), "+f"(c[3])
        : "r"(a[0]), "r"(a[1]), "r"(a[2]), "r"(a[3]), "r"(b[0]), "r"(b[1]));
}

// ---------------- fp32 -> fp16 converts --------------------------------------
__global__ void cvt_x_f16(const float* __restrict__ src, int n8){
    int i = blockIdx.x*blockDim.x + threadIdx.x;
    if (i >= n8) return;
    float4 a = ((const float4*)src)[2*i];
    float4 b = ((const float4*)src)[2*i + 1];
    uint4 o;
    o.x = packh2(a.x, a.y); o.y = packh2(a.z, a.w);
    o.z = packh2(b.x, b.y); o.w = packh2(b.z, b.w);
    ((uint4*)g_xh)[i] = o;
}
__global__ void cvt_w_f16(const float* __restrict__ w0, const float* __restrict__ w1,
                          const float* __restrict__ w2, const float* __restrict__ w3,
                          int n8){
    int i = blockIdx.x*blockDim.x + threadIdx.x;
    if (i >= n8) return;
    int z = blockIdx.y;
    const float* src = (z == 0) ? w0 : (z == 1) ? w1 : (z == 2) ? w2 : w3;
    __half* dst = g_wh + (size_t)z*DIMC*DIMC;
    float4 a = ((const float4*)src)[2*i];
    float4 b = ((const float4*)src)[2*i + 1];
    uint4 o;
    o.x = packh2(a.x, a.y); o.y = packh2(a.z, a.w);
    o.z = packh2(b.x, b.y); o.w = packh2(b.z, b.w);
    ((uint4*)dst)[i] = o;
}

// ============================================================================
// fp16 GEMM:  C[M,N] = A[M,K] @ W[N,K]^T   (both K-major fp16, K=1024)
// 128x128 tile, 4 warps (2x2), warp tile 64x64, BK=32, 3-stage cp.async,
// ldmatrix fragments, rows padded to 80 B. 2 CTAs/SM (no reg cap -> no spill).
// ============================================================================
#define BM 128
#define BN 128
#define BK 32
#define GNT (DIMC/BK)       // 32
#define ROWH 40             // halves per smem row (80 B)
#define AST (BM*ROWH)       // halves per operand tile: 5120
#define STAGE_H (2*AST)     // 10240 halves = 20480 B
#define NSTG 3
#define GSMEM_BYTES (NSTG*STAGE_H*2)   // 61440

__device__ __forceinline__ void g_fill(uint32_t sbase, int st,
                                       const __half* __restrict__ A,
                                       const __half* __restrict__ W,
                                       int bm0, int bn0, int kt, int tid){
    uint32_t sd = sbase + (uint32_t)(st*STAGE_H*2);
    #pragma unroll
    for (int p = 0; p < 4; p++){
        int n = tid + p*128;          // 0..511
        int r = n >> 2, ch = n & 3;
        cp16(sd + (uint32_t)(r*80 + ch*16),
             A + (size_t)(bm0 + r)*DIMC + kt*BK + ch*8);
    }
    #pragma unroll
    for (int p = 0; p < 4; p++){
        int n = tid + p*128;
        int r = n >> 2, ch = n & 3;
        cp16(sd + (uint32_t)(AST*2 + r*80 + ch*16),
             W + (size_t)(bn0 + r)*DIMC + kt*BK + ch*8);
    }
}

__global__ void __launch_bounds__(128, 2)
gemm_f16(float* __restrict__ Cout, int qkv)
{
    extern __shared__ __align__(16) __half sm[];
    uint32_t sbase = smem_u32(sm);
    int tid = threadIdx.x, lane = tid & 31, warp = tid >> 5;
    int bm0 = blockIdx.y*BM, bn0 = blockIdx.x*BN;
    int z = qkv ? (int)blockIdx.z : 3;
    const __half* A = qkv ? g_xh : g_attn;
    const __half* W = g_wh + (size_t)z*DIMC*DIMC;
    int wm = (warp >> 1)*64, wn = (warp & 1)*64;

    // per-lane ldmatrix byte offsets (hoisted out of the hot loop)
    uint32_t aOff = (uint32_t)((wm + (lane & 15))*80 + ((lane & 16) ? 16 : 0));
    uint32_t bOff = (uint32_t)(AST*2 + (wn + (lane & 7) + ((lane & 16) ? 8 : 0))*80
                               + ((lane & 8) << 1));

    float c[4][8][4];
    #pragma unroll
    for (int i = 0; i < 4; i++)
        #pragma unroll
        for (int j = 0; j < 8; j++)
            #pragma unroll
            for (int k = 0; k < 4; k++) c[i][j][k] = 0.f;

    g_fill(sbase, 0, A, W, bm0, bn0, 0, tid); CP_COMMIT();
    g_fill(sbase, 1, A, W, bm0, bn0, 1, tid); CP_COMMIT();

    for (int kt = 0; kt < GNT; kt++){
        int s = kt % 3;
        if (kt < GNT-1) { CP_WAIT(1); } else { CP_WAIT(0); }
        __syncthreads();
        if (kt + 2 < GNT){
            g_fill(sbase, (kt+2) % 3, A, W, bm0, bn0, kt+2, tid);
            CP_COMMIT();
        }

        uint32_t sa = sbase + (uint32_t)(s*STAGE_H*2);
        #pragma unroll
        for (int ks = 0; ks < 2; ks++){
            uint32_t af[4][4];
            #pragma unroll
            for (int mt = 0; mt < 4; mt++)
                ldsm_x4(af[mt][0], af[mt][1], af[mt][2], af[mt][3],
                        sa + aOff + (uint32_t)(mt*1280 + ks*32));
            uint32_t bf[8][2];
            #pragma unroll
            for (int np = 0; np < 4; np++){
                uint32_t r0, r1, r2, r3;
                ldsm_x4(r0, r1, r2, r3, sa + bOff + (uint32_t)(np*1280 + ks*32));
                bf[np*2][0]   = r0; bf[np*2][1]   = r1;
                bf[np*2+1][0] = r2; bf[np*2+1][1] = r3;
            }
            #pragma unroll
            for (int mt = 0; mt < 4; mt++)
                #pragma unroll
                for (int nt = 0; nt < 8; nt++)
                    mma_f16(c[mt][nt], af[mt], bf[nt]);
        }
    }

    // epilogue. Q gets softmax scale + log2e folded in (exp2-domain softmax).
    float sc = (qkv && z == 0) ? 0.125f*1.44269504088896f : 1.0f;
    #pragma unroll
    for (int mt = 0; mt < 4; mt++){
        #pragma unroll
        for (int nt = 0; nt < 8; nt++){
            int gr = bm0 + wm + mt*16 + (lane >> 2);
            int gc = bn0 + wn + nt*8 + ((lane & 3) << 1);
            if (qkv){
                __half* dst = (z == 0) ? g_q : (z == 1) ? g_k : g_v;
                int bb = gr >> 11, tt = gr & (SEQ - 1);
                int hh = gc >> 6,  dd = gc & (HD - 1);
                size_t off = ((size_t)(bb*NH + hh)*SEQ + tt)*HD + dd;
                *(uint32_t*)(dst + off)         = packh2(c[mt][nt][0]*sc, c[mt][nt][1]*sc);
                *(uint32_t*)(dst + off + 8*HD)  = packh2(c[mt][nt][2]*sc, c[mt][nt][3]*sc);
            } else {
                *(float2*)(Cout + (size_t)gr*DIMC + gc)
                    = make_float2(c[mt][nt][0], c[mt][nt][1]);
                *(float2*)(Cout + (size_t)(gr + 8)*DIMC + gc)
                    = make_float2(c[mt][nt][2], c[mt][nt][3]);
            }
        }
    }
}

// ============================================================================
// causal flash attention: fp16 mma (m16n8k16), exp2-domain softmax with
// f16x2-vectorized exponentials (ex2 output IS the P fragment), ldmatrix
// frags, 3-stage cp.async K/V pipeline. 4 warps x 16 q-rows, QT=64, KTILE=32.
// q-tiles assigned in REVERSE order (longest CTAs first) for wave balance.
// ============================================================================
#define QT 64
#define KTILE 32
#define ARH 72                 // halves per row (144 B)
#define KVSTRIDE (KTILE*ARH*2) // 9216 B per K (or V) stage

__global__ void __launch_bounds__(128, 4)
attn_f16()
{
    __shared__ __align__(16) __half sQ[QT*ARH];          //  9216 B
    __shared__ __align__(16) __half sK[3][KTILE*ARH];    // 13824 B
    __shared__ __align__(16) __half sV[3][KTILE*ARH];    // 13824 B

    int tid  = threadIdx.x;
    int lane = tid & 31;
    int warp = tid >> 5;
    int bh = blockIdx.y;
    int q0 = ((int)gridDim.x - 1 - (int)blockIdx.x) * QT;   // longest first

    const __half* Qg = g_q + (size_t)bh*SEQ*HD;
    const __half* Kg = g_k + (size_t)bh*SEQ*HD;
    const __half* Vg = g_v + (size_t)bh*SEQ*HD;

    uint32_t sQb = smem_u32(sQ);
    uint32_t sK0 = smem_u32(sK[0]);
    uint32_t sV0 = smem_u32(sV[0]);
    int nkt = (q0 + QT) / KTILE;   // >= 2 always

    // per-lane ldmatrix byte offsets (loop-invariant)
    uint32_t kOff = (uint32_t)(((lane & 7) + ((lane & 16) ? 8 : 0))*144 + ((lane & 8) << 1));
    uint32_t vOff = (uint32_t)(((lane & 7) + ((lane & 8) ? 8 : 0))*144 + ((lane & 16) ? 16 : 0));

    // prologue: Q + KV stage 0 in group 0; KV stage 1 in group 1
    #pragma unroll
    for (int p = 0; p < 4; p++){
        int n = tid + p*128;           // 0..511
        int r = n >> 3, ch = n & 7;
        cp16(sQb + (uint32_t)(r*144 + ch*16), Qg + (size_t)(q0 + r)*HD + ch*8);
    }
    #pragma unroll
    for (int p = 0; p < 4; p++){
        int n = tid + p*128;
        int isV = n >> 8, m = n & 255;
        int r = m >> 3, ch = m & 7;
        cp16((isV ? sV0 : sK0) + (uint32_t)(r*144 + ch*16),
             (isV ? Vg : Kg) + (size_t)r*HD + ch*8);
    }
    CP_COMMIT();
    #pragma unroll
    for (int p = 0; p < 4; p++){
        int n = tid + p*128;
        int isV = n >> 8, m = n & 255;
        int r = m >> 3, ch = m & 7;
        cp16((isV ? sV0 : sK0) + (uint32_t)(KVSTRIDE + r*144 + ch*16),
             (isV ? Vg : Kg) + (size_t)(KTILE + r)*HD + ch*8);
    }
    CP_COMMIT();

    uint32_t qf[4][4];
    float o[8][4];
    #pragma unroll
    for (int i = 0; i < 8; i++)
        #pragma unroll
        for (int j = 0; j < 4; j++) o[i][j] = 0.f;
    float m0 = -1e30f, m1 = -1e30f, l0 = 0.f, l1 = 0.f;

    uint32_t stOff = 0;           // rotating stage byte-offset (0, 9216, 18432)
    for (int kt = 0; kt < nkt; kt++){
        if (kt < nkt-1) { CP_WAIT(1); } else { CP_WAIT(0); }
        __syncthreads();
        if (kt + 2 < nkt){
            uint32_t nOff = stOff + 2u*KVSTRIDE;
            if (nOff >= 3u*KVSTRIDE) nOff -= 3u*KVSTRIDE;
            int kb2 = (kt+2)*KTILE;
            #pragma unroll
            for (int p = 0; p < 4; p++){
                int n = tid + p*128;
                int isV = n >> 8, m = n & 255;
                int r = m >> 3, ch = m & 7;
                cp16((isV ? sV0 : sK0) + nOff + (uint32_t)(r*144 + ch*16),
                     (isV ? Vg : Kg) + (size_t)(kb2 + r)*HD + ch*8);
            }
            CP_COMMIT();
        }
        if (kt == 0){
            #pragma unroll
            for (int ks = 0; ks < 4; ks++){
                int row = warp*16 + (lane & 15);
                int col = ks*16 + ((lane & 16) ? 8 : 0);
                ldsm_x4(qf[ks][0], qf[ks][1], qf[ks][2], qf[ks][3],
                        sQb + (uint32_t)(row*144 + col*2));
            }
        }

        int kb = kt*KTILE;
        int wrow0 = q0 + warp*16;
        if (kb <= wrow0 + 15){   // tile not fully masked for this warp
            uint32_t sKb = sK0 + stOff;
            uint32_t sVb = sV0 + stOff;

            // S = Q @ K^T  (16 q-rows x 32 keys); Q pre-scaled by log2e/8
            float sv[4][4];
            #pragma unroll
            for (int i = 0; i < 4; i++)
                #pragma unroll
                for (int j = 0; j < 4; j++) sv[i][j] = 0.f;
            #pragma unroll
            for (int ks = 0; ks < 4; ks++){
                uint32_t kf[4][2];
                #pragma unroll
                for (int np = 0; np < 2; np++){
                    uint32_t r0, r1, r2, r3;
                    ldsm_x4(r0, r1, r2, r3, sKb + kOff + (uint32_t)(np*2304 + ks*32));
                    kf[np*2][0]   = r0; kf[np*2][1]   = r1;
                    kf[np*2+1][0] = r2; kf[np*2+1][1] = r3;
                }
                #pragma unroll
                for (int nt = 0; nt < 4; nt++)
                    mma_f16(sv[nt], qf[ks], kf[nt]);
            }

            // causal mask (diagonal tiles only)
            int qr0 = wrow0 + (lane >> 2);
            if (kb + KTILE - 1 > wrow0){
                #pragma unroll
                for (int nt = 0; nt < 4; nt++){
                    int kc = kb + nt*8 + ((lane & 3) << 1);
                    if (kc     > qr0    ) sv[nt][0] = -1e30f;
                    if (kc + 1 > qr0    ) sv[nt][1] = -1e30f;
                    if (kc     > qr0 + 8) sv[nt][2] = -1e30f;
                    if (kc + 1 > qr0 + 8) sv[nt][3] = -1e30f;
                }
            }

            // online softmax, exp2 domain (rows qr0 and qr0+8 per lane-quad)
            float rm0 = -1e30f, rm1 = -1e30f;
            #pragma unroll
            for (int nt = 0; nt < 4; nt++){
                rm0 = fmaxf(rm0, fmaxf(sv[nt][0], sv[nt][1]));
                rm1 = fmaxf(rm1, fmaxf(sv[nt][2], sv[nt][3]));
            }
            rm0 = fmaxf(rm0, __shfl_xor_sync(0xffffffffu, rm0, 1));
            rm0 = fmaxf(rm0, __shfl_xor_sync(0xffffffffu, rm0, 2));
            rm1 = fmaxf(rm1, __shfl_xor_sync(0xffffffffu, rm1, 1));
            rm1 = fmaxf(rm1, __shfl_xor_sync(0xffffffffu, rm1, 2));

            float mn0 = fmaxf(m0, rm0), mn1 = fmaxf(m1, rm1);
            float a0 = ex2(m0 - mn0), a1 = ex2(m1 - mn1);

            // P = ex2(S - mn) computed directly in f16x2: ph[] IS the
            // A-fragment of the P@V mma (ph[4j+k] = pf[j][k]).
            uint32_t ph[8];
            #pragma unroll
            for (int nt = 0; nt < 4; nt++){
                ph[2*nt]   = packh2(sv[nt][0] - mn0, sv[nt][1] - mn0);
                ph[2*nt+1] = packh2(sv[nt][2] - mn1, sv[nt][3] - mn1);
            }
            #pragma unroll
            for (int i = 0; i < 8; i++) ph[i] = ex2h2(ph[i]);

            // row sums via f16x2 tree (partials <= 4 -> err ~1e-4), fp32 finish
            uint32_t h0 = hadd2(hadd2(ph[0], ph[2]), hadd2(ph[4], ph[6]));
            uint32_t h1 = hadd2(hadd2(ph[1], ph[3]), hadd2(ph[5], ph[7]));
            float2 f0 = h2f2(h0), f1 = h2f2(h1);
            float rs0 = f0.x + f0.y;
            float rs1 = f1.x + f1.y;
            rs0 += __shfl_xor_sync(0xffffffffu, rs0, 1);
            rs0 += __shfl_xor_sync(0xffffffffu, rs0, 2);
            rs1 += __shfl_xor_sync(0xffffffffu, rs1, 1);
            rs1 += __shfl_xor_sync(0xffffffffu, rs1, 2);
            l0 = l0*a0 + rs0;
            l1 = l1*a1 + rs1;
            m0 = mn0; m1 = mn1;
            #pragma unroll
            for (int nt = 0; nt < 8; nt++){
                o[nt][0] *= a0; o[nt][1] *= a0;
                o[nt][2] *= a1; o[nt][3] *= a1;
            }

            // O += P @ V  (V fragments via ldmatrix.trans)
            #pragma unroll
            for (int j = 0; j < 2; j++){
                uint32_t vf[8][2];
                #pragma unroll
                for (int np = 0; np < 4; np++){
                    uint32_t r0, r1, r2, r3;
                    ldsm_x4t(r0, r1, r2, r3, sVb + vOff + (uint32_t)(j*2304 + np*32));
                    vf[np*2][0]   = r0; vf[np*2][1]   = r1;
                    vf[np*2+1][0] = r2; vf[np*2+1][1] = r3;
                }
                #pragma unroll
                for (int nt = 0; nt < 8; nt++)
                    mma_f16(o[nt], ph + 4*j, vf[nt]);
            }
        }
        stOff += KVSTRIDE;
        if (stOff >= 3u*KVSTRIDE) stOff = 0;
    }

    // epilogue: O/l -> g_attn (fp16) [b*T+t][h*64+d]
    float il0 = 1.0f / l0, il1 = 1.0f / l1;
    int b = bh >> 4, h = bh & 15;
    int t0 = q0 + warp*16 + (lane >> 2);
    #pragma unroll
    for (int nt = 0; nt < 8; nt++){
        int d = nt*8 + ((lane & 3) << 1);
        size_t base = ((size_t)(b*SEQ + t0))*DIMC + h*HD + d;
        *(uint32_t*)(g_attn + base)                  = packh2(o[nt][0]*il0, o[nt][1]*il0);
        *(uint32_t*)(g_attn + base + (size_t)8*DIMC) = packh2(o[nt][2]*il1, o[nt][3]*il1);
    }
}

// ---------------- launch ----------------------------------------------------
extern "C" void kernel_launch(void* const* d_in, const int* in_sizes, int n_in,
                              void* d_out, int out_size)
{
    const float* x  = (const float*)d_in[0];
    const float* wq = (const float*)d_in[1];
    const float* wk = (const float*)d_in[2];
    const float* wv = (const float*)d_in[3];
    const float* wo = (const float*)d_in[4];
    float* out = (float*)d_out;

    cudaFuncSetAttribute(gemm_f16, cudaFuncAttributeMaxDynamicSharedMemorySize, GSMEM_BYTES);

    // fp32 -> fp16 converts
    int n8x = MTOT*DIMC/8;     // 1048576
    int n8w = DIMC*DIMC/8;     // 131072
    cvt_x_f16<<<(n8x+255)/256, 256>>>(x, n8x);
    cvt_w_f16<<<dim3((n8w+255)/256, 4), 256>>>(wq, wk, wv, wo, n8w);

    dim3 gq(DIMC/BN, MTOT/BM, 3);   // fused QKV
    gemm_f16<<<gq, 128, GSMEM_BYTES>>>(nullptr, 1);
    attn_f16<<<dim3(SEQ/QT, BATCH*NH), 128>>>();
    dim3 go(DIMC/BN, MTOT/BM, 1);
    gemm_f16<<<go, 128, GSMEM_BYTES>>>(out, 0);
}

// round 11
// speedup vs baseline: 2.6601x; 1.0349x over previous
#include <cuda_runtime.h>
#include <cuda_fp16.h>
#include <cstdint>

#define DIMC  1024
#define NH    16
#define HD    64
#define BATCH 4
#define SEQ   2048
#define MTOT  (BATCH*SEQ)   // 8192

// ---------------- scratch (device globals; no allocation allowed) ----------
__device__ __half g_xh[(size_t)MTOT*DIMC];        // x in fp16
__device__ __half g_wh[(size_t)4*DIMC*DIMC];      // wq,wk,wv,wo in fp16
__device__ __half g_q[(size_t)MTOT*DIMC];         // [b*NH+h][t][d], pre-scaled by log2e/8
__device__ __half g_k[(size_t)MTOT*DIMC];
__device__ __half g_v[(size_t)MTOT*DIMC];
__device__ __half g_attn[(size_t)MTOT*DIMC];      // [b*T+t][h*64+d]

// ---------------- helpers ---------------------------------------------------
__device__ __forceinline__ uint32_t smem_u32(const void* p){
    uint32_t a;
    asm("{ .reg .u64 t; cvta.to.shared.u64 t, %1; cvt.u32.u64 %0, t; }" : "=r"(a) : "l"(p));
    return a;
}
// pack two f32 -> f16x2 (lo, hi). PTX cvt f16x2: first source -> HIGH half.
__device__ __forceinline__ uint32_t packh2(float lo, float hi){
    uint32_t d;
    asm("cvt.rn.f16x2.f32 %0, %1, %2;" : "=r"(d) : "f"(hi), "f"(lo));
    return d;
}
__device__ __forceinline__ float ex2(float x){
    float r; asm("ex2.approx.f32 %0, %1;" : "=f"(r) : "f"(x)); return r;
}
__device__ __forceinline__ void cp16(uint32_t dst, const void* src){
    asm volatile("cp.async.cg.shared.global [%0], [%1], 16;" :: "r"(dst), "l"(src));
}
#define CP_COMMIT() asm volatile("cp.async.commit_group;" ::: "memory")
#define CP_WAIT(n)  asm volatile("cp.async.wait_group %0;" :: "n"(n) : "memory")

__device__ __forceinline__ void ldsm_x4(uint32_t& r0, uint32_t& r1, uint32_t& r2, uint32_t& r3,
                                        uint32_t addr){
    asm volatile("ldmatrix.sync.aligned.m8n8.x4.shared.b16 {%0,%1,%2,%3}, [%4];"
                 : "=r"(r0), "=r"(r1), "=r"(r2), "=r"(r3) : "r"(addr));
}
__device__ __forceinline__ void ldsm_x4t(uint32_t& r0, uint32_t& r1, uint32_t& r2, uint32_t& r3,
                                         uint32_t addr){
    asm volatile("ldmatrix.sync.aligned.m8n8.x4.trans.shared.b16 {%0,%1,%2,%3}, [%4];"
                 : "=r"(r0), "=r"(r1), "=r"(r2), "=r"(r3) : "r"(addr));
}
__device__ __forceinline__ void mma_f16(float c[4], const uint32_t a[4], const uint32_t b[2]){
    asm volatile(
        "mma.sync.aligned.m16n8k16.row.col.f32.f16.f16.f32 "
        "{%0,%1,%2,%3}, {%4,%5,%6,%7}, {%8,%9}, {%0,%1,%2,%3};"
        : "+f"(c[0]), "+f"(c[1]), "+f"(c[2]), "+f"(c[3])
        : "r"(a[0]), "r"(a[1]), "r"(a[2]), "r"(a[3]), "r"(b[0]), "r"(b[1]));
}

// ---------------- fp32 -> fp16 converts --------------------------------------
__global__ void cvt_x_f16(const float* __restrict__ src, int n8){
    int i = blockIdx.x*blockDim.x + threadIdx.x;
    if (i >= n8) return;
    float4 a = ((const float4*)src)[2*i];
    float4 b = ((const float4*)src)[2*i + 1];
    uint4 o;
    o.x = packh2(a.x, a.y); o.y = packh2(a.z, a.w);
    o.z = packh2(b.x, b.y); o.w = packh2(b.z, b.w);
    ((uint4*)g_xh)[i] = o;
}
__global__ void cvt_w_f16(const float* __restrict__ w0, const float* __restrict__ w1,
                          const float* __restrict__ w2, const float* __restrict__ w3,
                          int n8){
    int i = blockIdx.x*blockDim.x + threadIdx.x;
    if (i >= n8) return;
    int z = blockIdx.y;
    const float* src = (z == 0) ? w0 : (z == 1) ? w1 : (z == 2) ? w2 : w3;
    __half* dst = g_wh + (size_t)z*DIMC*DIMC;
    float4 a = ((const float4*)src)[2*i];
    float4 b = ((const float4*)src)[2*i + 1];
    uint4 o;
    o.x = packh2(a.x, a.y); o.y = packh2(a.z, a.w);
    o.z = packh2(b.x, b.y); o.w = packh2(b.z, b.w);
    ((uint4*)dst)[i] = o;
}

// ============================================================================
// fp16 GEMM:  C[M,N] = A[M,K] @ W[N,K]^T   (both K-major fp16, K=1024)
// 128x128 tile, 4 warps (2x2), warp tile 64x64, BK=32, 3-stage cp.async,
// ldmatrix fragments, rows padded to 80 B. 2 CTAs/SM (no reg cap -> no spill).
// ============================================================================
#define BM 128
#define BN 128
#define BK 32
#define GNT (DIMC/BK)       // 32
#define ROWH 40             // halves per smem row (80 B)
#define AST (BM*ROWH)       // halves per operand tile: 5120
#define STAGE_H (2*AST)     // 10240 halves = 20480 B
#define NSTG 3
#define GSMEM_BYTES (NSTG*STAGE_H*2)   // 61440

__device__ __forceinline__ void g_fill(uint32_t sbase, int st,
                                       const __half* __restrict__ A,
                                       const __half* __restrict__ W,
                                       int bm0, int bn0, int kt, int tid){
    uint32_t sd = sbase + (uint32_t)(st*STAGE_H*2);
    #pragma unroll
    for (int p = 0; p < 4; p++){
        int n = tid + p*128;          // 0..511
        int r = n >> 2, ch = n & 3;
        cp16(sd + (uint32_t)(r*80 + ch*16),
             A + (size_t)(bm0 + r)*DIMC + kt*BK + ch*8);
    }
    #pragma unroll
    for (int p = 0; p < 4; p++){
        int n = tid + p*128;
        int r = n >> 2, ch = n & 3;
        cp16(sd + (uint32_t)(AST*2 + r*80 + ch*16),
             W + (size_t)(bn0 + r)*DIMC + kt*BK + ch*8);
    }
}

__global__ void __launch_bounds__(128, 2)
gemm_f16(float* __restrict__ Cout, int qkv)
{
    extern __shared__ __align__(16) __half sm[];
    uint32_t sbase = smem_u32(sm);
    int tid = threadIdx.x, lane = tid & 31, warp = tid >> 5;
    int bm0 = blockIdx.y*BM, bn0 = blockIdx.x*BN;
    int z = qkv ? (int)blockIdx.z : 3;
    const __half* A = qkv ? g_xh : g_attn;
    const __half* W = g_wh + (size_t)z*DIMC*DIMC;
    int wm = (warp >> 1)*64, wn = (warp & 1)*64;

    // per-lane ldmatrix byte offsets (hoisted out of the hot loop)
    uint32_t aOff = (uint32_t)((wm + (lane & 15))*80 + ((lane & 16) ? 16 : 0));
    uint32_t bOff = (uint32_t)(AST*2 + (wn + (lane & 7) + ((lane & 16) ? 8 : 0))*80
                               + ((lane & 8) << 1));

    float c[4][8][4];
    #pragma unroll
    for (int i = 0; i < 4; i++)
        #pragma unroll
        for (int j = 0; j < 8; j++)
            #pragma unroll
            for (int k = 0; k < 4; k++) c[i][j][k] = 0.f;

    g_fill(sbase, 0, A, W, bm0, bn0, 0, tid); CP_COMMIT();
    g_fill(sbase, 1, A, W, bm0, bn0, 1, tid); CP_COMMIT();

    for (int kt = 0; kt < GNT; kt++){
        int s = kt % 3;
        if (kt < GNT-1) { CP_WAIT(1); } else { CP_WAIT(0); }
        __syncthreads();
        if (kt + 2 < GNT){
            g_fill(sbase, (kt+2) % 3, A, W, bm0, bn0, kt+2, tid);
            CP_COMMIT();
        }

        uint32_t sa = sbase + (uint32_t)(s*STAGE_H*2);
        #pragma unroll
        for (int ks = 0; ks < 2; ks++){
            uint32_t af[4][4];
            #pragma unroll
            for (int mt = 0; mt < 4; mt++)
                ldsm_x4(af[mt][0], af[mt][1], af[mt][2], af[mt][3],
                        sa + aOff + (uint32_t)(mt*1280 + ks*32));
            uint32_t bf[8][2];
            #pragma unroll
            for (int np = 0; np < 4; np++){
                uint32_t r0, r1, r2, r3;
                ldsm_x4(r0, r1, r2, r3, sa + bOff + (uint32_t)(np*1280 + ks*32));
                bf[np*2][0]   = r0; bf[np*2][1]   = r1;
                bf[np*2+1][0] = r2; bf[np*2+1][1] = r3;
            }
            #pragma unroll
            for (int mt = 0; mt < 4; mt++)
                #pragma unroll
                for (int nt = 0; nt < 8; nt++)
                    mma_f16(c[mt][nt], af[mt], bf[nt]);
        }
    }

    // epilogue. Q gets softmax scale + log2e folded in (exp2-domain softmax).
    float sc = (qkv && z == 0) ? 0.125f*1.44269504088896f : 1.0f;
    #pragma unroll
    for (int mt = 0; mt < 4; mt++){
        #pragma unroll
        for (int nt = 0; nt < 8; nt++){
            int gr = bm0 + wm + mt*16 + (lane >> 2);
            int gc = bn0 + wn + nt*8 + ((lane & 3) << 1);
            if (qkv){
                __half* dst = (z == 0) ? g_q : (z == 1) ? g_k : g_v;
                int bb = gr >> 11, tt = gr & (SEQ - 1);
                int hh = gc >> 6,  dd = gc & (HD - 1);
                size_t off = ((size_t)(bb*NH + hh)*SEQ + tt)*HD + dd;
                *(uint32_t*)(dst + off)         = packh2(c[mt][nt][0]*sc, c[mt][nt][1]*sc);
                *(uint32_t*)(dst + off + 8*HD)  = packh2(c[mt][nt][2]*sc, c[mt][nt][3]*sc);
            } else {
                *(float2*)(Cout + (size_t)gr*DIMC + gc)
                    = make_float2(c[mt][nt][0], c[mt][nt][1]);
                *(float2*)(Cout + (size_t)(gr + 8)*DIMC + gc)
                    = make_float2(c[mt][nt][2], c[mt][nt][3]);
            }
        }
    }
}

// ============================================================================
// causal flash attention: fp16 mma (m16n8k16), exp2-domain fp32 softmax,
// KTILE=64 (softmax bookkeeping amortized over 2x keys), 2-stage cp.async
// double buffer, ldmatrix frags, register-only P re-frag.
// 4 warps x 16 q-rows, QT=64, rows 144 B. Reverse q-tile order (wave balance).
// ============================================================================
#define QT 64
#define KTILE 64
#define ARH 72                 // halves per row (144 B)
#define KVSTRIDE (KTILE*ARH*2) // 18432 B per K (or V) stage

__global__ void __launch_bounds__(128, 3)
attn_f16()
{
    __shared__ __align__(16) __half sQ[QT*ARH];          //  9216 B
    __shared__ __align__(16) __half sK[2][KTILE*ARH];    // 18432 B
    __shared__ __align__(16) __half sV[2][KTILE*ARH];    // 18432 B  -> 46080 B

    int tid  = threadIdx.x;
    int lane = tid & 31;
    int warp = tid >> 5;
    int bh = blockIdx.y;
    int q0 = ((int)gridDim.x - 1 - (int)blockIdx.x) * QT;   // longest first

    const __half* Qg = g_q + (size_t)bh*SEQ*HD;
    const __half* Kg = g_k + (size_t)bh*SEQ*HD;
    const __half* Vg = g_v + (size_t)bh*SEQ*HD;

    uint32_t sQb = smem_u32(sQ);
    uint32_t sK0 = smem_u32(sK[0]);
    uint32_t sV0 = smem_u32(sV[0]);
    int nkt = q0/KTILE + 1;      // >= 1

    // per-lane ldmatrix byte offsets (loop-invariant)
    uint32_t kOff = (uint32_t)(((lane & 7) + ((lane & 16) ? 8 : 0))*144 + ((lane & 8) << 1));
    uint32_t vOff = (uint32_t)(((lane & 7) + ((lane & 8) ? 8 : 0))*144 + ((lane & 16) ? 16 : 0));

    // prologue: Q + KV stage 0 in one group
    #pragma unroll
    for (int p = 0; p < 4; p++){
        int n = tid + p*128;           // 0..511
        int r = n >> 3, ch = n & 7;
        cp16(sQb + (uint32_t)(r*144 + ch*16), Qg + (size_t)(q0 + r)*HD + ch*8);
    }
    #pragma unroll
    for (int p = 0; p < 8; p++){
        int n = tid + p*128;           // 0..1023
        int isV = n >> 9, m = n & 511;
        int r = m >> 3, ch = m & 7;    // r 0..63
        cp16((isV ? sV0 : sK0) + (uint32_t)(r*144 + ch*16),
             (isV ? Vg : Kg) + (size_t)r*HD + ch*8);
    }
    CP_COMMIT();

    uint32_t qf[4][4];
    float o[8][4];
    #pragma unroll
    for (int i = 0; i < 8; i++)
        #pragma unroll
        for (int j = 0; j < 4; j++) o[i][j] = 0.f;
    float m0 = -1e30f, m1 = -1e30f, l0 = 0.f, l1 = 0.f;

    for (int kt = 0; kt < nkt; kt++){
        CP_WAIT(0);            // stage kt (and Q on kt=0) has landed
        __syncthreads();       // all warps done reading the other buffer
        if (kt + 1 < nkt){     // prefetch stage kt+1 into the other buffer
            uint32_t bOf = ((kt+1) & 1) ? (uint32_t)KVSTRIDE : 0u;
            int kb2 = (kt+1)*KTILE;
            #pragma unroll
            for (int p = 0; p < 8; p++){
                int n = tid + p*128;
                int isV = n >> 9, m = n & 511;
                int r = m >> 3, ch = m & 7;
                cp16((isV ? sV0 : sK0) + bOf + (uint32_t)(r*144 + ch*16),
                     (isV ? Vg : Kg) + (size_t)(kb2 + r)*HD + ch*8);
            }
            CP_COMMIT();
        }
        if (kt == 0){
            #pragma unroll
            for (int ks = 0; ks < 4; ks++){
                int row = warp*16 + (lane & 15);
                int col = ks*16 + ((lane & 16) ? 8 : 0);
                ldsm_x4(qf[ks][0], qf[ks][1], qf[ks][2], qf[ks][3],
                        sQb + (uint32_t)(row*144 + col*2));
            }
        }

        int kb = kt*KTILE;
        int wrow0 = q0 + warp*16;
        uint32_t stO = (kt & 1) ? (uint32_t)KVSTRIDE : 0u;
        uint32_t sKb = sK0 + stO;
        uint32_t sVb = sV0 + stO;

        // S = Q @ K^T  (16 q-rows x 64 keys); Q pre-scaled by log2e/8
        float sv[8][4];
        #pragma unroll
        for (int i = 0; i < 8; i++)
            #pragma unroll
            for (int j = 0; j < 4; j++) sv[i][j] = 0.f;
        #pragma unroll
        for (int ks = 0; ks < 4; ks++){
            uint32_t kf[8][2];
            #pragma unroll
            for (int np = 0; np < 4; np++){
                uint32_t r0, r1, r2, r3;
                ldsm_x4(r0, r1, r2, r3, sKb + kOff + (uint32_t)(np*2304 + ks*32));
                kf[np*2][0]   = r0; kf[np*2][1]   = r1;
                kf[np*2+1][0] = r2; kf[np*2+1][1] = r3;
            }
            #pragma unroll
            for (int nt = 0; nt < 8; nt++)
                mma_f16(sv[nt], qf[ks], kf[nt]);
        }

        // causal mask (last tile only: kb == q0)
        int qr0 = wrow0 + (lane >> 2);
        if (kb + KTILE - 1 > wrow0){
            #pragma unroll
            for (int nt = 0; nt < 8; nt++){
                int kc = kb + nt*8 + ((lane & 3) << 1);
                if (kc     > qr0    ) sv[nt][0] = -1e30f;
                if (kc + 1 > qr0    ) sv[nt][1] = -1e30f;
                if (kc     > qr0 + 8) sv[nt][2] = -1e30f;
                if (kc + 1 > qr0 + 8) sv[nt][3] = -1e30f;
            }
        }

        // online softmax, exp2 domain (rows qr0 and qr0+8 per lane-quad)
        float rm0 = -1e30f, rm1 = -1e30f;
        #pragma unroll
        for (int nt = 0; nt < 8; nt++){
            rm0 = fmaxf(rm0, fmaxf(sv[nt][0], sv[nt][1]));
            rm1 = fmaxf(rm1, fmaxf(sv[nt][2], sv[nt][3]));
        }
        rm0 = fmaxf(rm0, __shfl_xor_sync(0xffffffffu, rm0, 1));
        rm0 = fmaxf(rm0, __shfl_xor_sync(0xffffffffu, rm0, 2));
        rm1 = fmaxf(rm1, __shfl_xor_sync(0xffffffffu, rm1, 1));
        rm1 = fmaxf(rm1, __shfl_xor_sync(0xffffffffu, rm1, 2));

        float mn0 = fmaxf(m0, rm0), mn1 = fmaxf(m1, rm1);
        float a0 = ex2(m0 - mn0), a1 = ex2(m1 - mn1);
        float rs0 = 0.f, rs1 = 0.f;
        #pragma unroll
        for (int nt = 0; nt < 8; nt++){
            sv[nt][0] = ex2(sv[nt][0] - mn0);
            sv[nt][1] = ex2(sv[nt][1] - mn0);
            sv[nt][2] = ex2(sv[nt][2] - mn1);
            sv[nt][3] = ex2(sv[nt][3] - mn1);
            rs0 += sv[nt][0] + sv[nt][1];
            rs1 += sv[nt][2] + sv[nt][3];
        }
        rs0 += __shfl_xor_sync(0xffffffffu, rs0, 1);
        rs0 += __shfl_xor_sync(0xffffffffu, rs0, 2);
        rs1 += __shfl_xor_sync(0xffffffffu, rs1, 1);
        rs1 += __shfl_xor_sync(0xffffffffu, rs1, 2);
        l0 = l0*a0 + rs0;
        l1 = l1*a1 + rs1;
        m0 = mn0; m1 = mn1;
        #pragma unroll
        for (int nt = 0; nt < 8; nt++){
            o[nt][0] *= a0; o[nt][1] *= a0;
            o[nt][2] *= a1; o[nt][3] *= a1;
        }

        // P: C-fragment -> A-fragment entirely in registers (4 k16-steps)
        uint32_t pf[4][4];
        #pragma unroll
        for (int j = 0; j < 4; j++){
            pf[j][0] = packh2(sv[2*j][0],   sv[2*j][1]);
            pf[j][1] = packh2(sv[2*j][2],   sv[2*j][3]);
            pf[j][2] = packh2(sv[2*j+1][0], sv[2*j+1][1]);
            pf[j][3] = packh2(sv[2*j+1][2], sv[2*j+1][3]);
        }

        // O += P @ V  (V fragments via ldmatrix.trans)
        #pragma unroll
        for (int j = 0; j < 4; j++){
            uint32_t vf[8][2];
            #pragma unroll
            for (int np = 0; np < 4; np++){
                uint32_t r0, r1, r2, r3;
                ldsm_x4t(r0, r1, r2, r3, sVb + vOff + (uint32_t)(j*2304 + np*32));
                vf[np*2][0]   = r0; vf[np*2][1]   = r1;
                vf[np*2+1][0] = r2; vf[np*2+1][1] = r3;
            }
            #pragma unroll
            for (int nt = 0; nt < 8; nt++)
                mma_f16(o[nt], pf[j], vf[nt]);
        }
    }

    // epilogue: O/l -> g_attn (fp16) [b*T+t][h*64+d]
    float il0 = 1.0f / l0, il1 = 1.0f / l1;
    int b = bh >> 4, h = bh & 15;
    int t0 = q0 + warp*16 + (lane >> 2);
    #pragma unroll
    for (int nt = 0; nt < 8; nt++){
        int d = nt*8 + ((lane & 3) << 1);
        size_t base = ((size_t)(b*SEQ + t0))*DIMC + h*HD + d;
        *(uint32_t*)(g_attn + base)                  = packh2(o[nt][0]*il0, o[nt][1]*il0);
        *(uint32_t*)(g_attn + base + (size_t)8*DIMC) = packh2(o[nt][2]*il1, o[nt][3]*il1);
    }
}

// ---------------- launch ----------------------------------------------------
extern "C" void kernel_launch(void* const* d_in, const int* in_sizes, int n_in,
                              void* d_out, int out_size)
{
    const float* x  = (const float*)d_in[0];
    const float* wq = (const float*)d_in[1];
    const float* wk = (const float*)d_in[2];
    const float* wv = (const float*)d_in[3];
    const float* wo = (const float*)d_in[4];
    float* out = (float*)d_out;

    cudaFuncSetAttribute(gemm_f16, cudaFuncAttributeMaxDynamicSharedMemorySize, GSMEM_BYTES);

    // fp32 -> fp16 converts
    int n8x = MTOT*DIMC/8;     // 1048576
    int n8w = DIMC*DIMC/8;     // 131072
    cvt_x_f16<<<(n8x+255)/256, 256>>>(x, n8x);
    cvt_w_f16<<<dim3((n8w+255)/256, 4), 256>>>(wq, wk, wv, wo, n8w);

    dim3 gq(DIMC/BN, MTOT/BM, 3);   // fused QKV
    gemm_f16<<<gq, 128, GSMEM_BYTES>>>(nullptr, 1);
    attn_f16<<<dim3(SEQ/QT, BATCH*NH), 128>>>();
    dim3 go(DIMC/BN, MTOT/BM, 1);
    gemm_f16<<<go, 128, GSMEM_BYTES>>>(out, 0);
}